// round 2
// baseline (speedup 1.0000x reference)
#include <cuda_runtime.h>
#include <cuda_bf16.h>
#include <stdint.h>
#include <math.h>

#define NB 64
#define NS 1024
#define NV 32000
#define NH 1024
// out: logits[64*32000] | h_new[2*64*1024] | c_new[2*64*1024] | attn[64*1024]
#define OUT_H   (NB*NV)
#define OUT_C   (OUT_H + 2*NB*NH)
#define OUT_ATT (OUT_C + 2*NB*NH)

__device__ float g_q[NB*1024];
__device__ float g_part[8*NB*NS];
__device__ float g_x[NB*2048];
__device__ float g_gates[NB*4096];
__device__ float g_h1[NB*NH];
__device__ float g_h2[NB*NH];

__device__ __forceinline__ float fast_tanh(float x){float y;asm("tanh.approx.f32 %0,%1;":"=f"(y):"f"(x));return y;}
__device__ __forceinline__ float to_tf32(float x){uint32_t u;asm("cvt.rna.tf32.f32 %0,%1;":"=r"(u):"f"(x));return __uint_as_float(u);}
__device__ __forceinline__ float sigf(float x){return 1.f/(1.f+expf(-x));}

__device__ __forceinline__ void mma_tf32(float* c,const uint32_t* a,const uint32_t* b){
    asm volatile("mma.sync.aligned.m16n8k8.row.col.f32.tf32.tf32.f32 "
        "{%0,%1,%2,%3},{%4,%5,%6,%7},{%8,%9},{%0,%1,%2,%3};\n"
        : "+f"(c[0]),"+f"(c[1]),"+f"(c[2]),"+f"(c[3])
        : "r"(a[0]),"r"(a[1]),"r"(a[2]),"r"(a[3]),"r"(b[0]),"r"(b[1]));
}

// ---- embed: g_x[b][0:1024] = emb[step[b]] ----
__global__ void embed_kernel(const int* __restrict__ step,const float* __restrict__ emb,float* __restrict__ x){
    int b=blockIdx.x; int idx=step[b];
    for(int j=threadIdx.x;j<1024;j+=256) x[b*2048+j]=emb[(size_t)idx*1024+j];
}

// ---- generic skinny GEMM: C[M<=64,N] = A[M,K]@B[N,K]^T (+bias or +=) ----
template<bool ACC>
__global__ void __launch_bounds__(128) gemm_tf32_kernel(
    const float* __restrict__ A,const float* __restrict__ Bm,float* __restrict__ C,
    int M,int N,int K,const float* __restrict__ bias1,const float* __restrict__ bias2)
{
    __shared__ float As[2][64][20];
    __shared__ float Bs[2][128][20];
    const int tid=threadIdx.x,lane=tid&31,warp=tid>>5;
    const int wm=warp&1,wn=warp>>1,g=lane>>2,t=lane&3;
    const int n0=blockIdx.x*128;
    float acc[2][8][4];
#pragma unroll
    for(int i=0;i<2;i++)
#pragma unroll
      for(int j=0;j<8;j++)
#pragma unroll
        for(int k=0;k<4;k++) acc[i][j][k]=0.f;
    float4 ra[2],rb[4];
    auto ldg=[&](int k0){
#pragma unroll
        for(int j=0;j<2;j++){int i=tid+128*j,r=i>>2,cb=i&3;
            ra[j]=*reinterpret_cast<const float4*>(A+(size_t)r*K+k0+cb*4);}
#pragma unroll
        for(int j=0;j<4;j++){int i=tid+128*j,r=i>>2,cb=i&3;
            rb[j]=*reinterpret_cast<const float4*>(Bm+(size_t)(n0+r)*K+k0+cb*4);}
    };
    auto sts=[&](int buf){
#pragma unroll
        for(int j=0;j<2;j++){int i=tid+128*j,r=i>>2,cb=i&3;
            As[buf][r][cb*4+0]=to_tf32(ra[j].x);As[buf][r][cb*4+1]=to_tf32(ra[j].y);
            As[buf][r][cb*4+2]=to_tf32(ra[j].z);As[buf][r][cb*4+3]=to_tf32(ra[j].w);}
#pragma unroll
        for(int j=0;j<4;j++){int i=tid+128*j,r=i>>2,cb=i&3;
            Bs[buf][r][cb*4+0]=to_tf32(rb[j].x);Bs[buf][r][cb*4+1]=to_tf32(rb[j].y);
            Bs[buf][r][cb*4+2]=to_tf32(rb[j].z);Bs[buf][r][cb*4+3]=to_tf32(rb[j].w);}
    };
    ldg(0);sts(0);__syncthreads();
    const int nst=K/16;
    for(int s=0;s<nst;s++){
        const int cur=s&1;
        if(s+1<nst) ldg((s+1)*16);
#pragma unroll
        for(int kk=0;kk<2;kk++){
            const int kb=kk*8;
            uint32_t af[2][4];
#pragma unroll
            for(int mi=0;mi<2;mi++){int mr=wm*32+mi*16;
                af[mi][0]=__float_as_uint(As[cur][mr+g][kb+t]);
                af[mi][1]=__float_as_uint(As[cur][mr+g+8][kb+t]);
                af[mi][2]=__float_as_uint(As[cur][mr+g][kb+t+4]);
                af[mi][3]=__float_as_uint(As[cur][mr+g+8][kb+t+4]);}
            uint32_t bf[8][2];
#pragma unroll
            for(int ni=0;ni<8;ni++){int nr=wn*64+ni*8+g;
                bf[ni][0]=__float_as_uint(Bs[cur][nr][kb+t]);
                bf[ni][1]=__float_as_uint(Bs[cur][nr][kb+t+4]);}
#pragma unroll
            for(int mi=0;mi<2;mi++)
#pragma unroll
                for(int ni=0;ni<8;ni++) mma_tf32(acc[mi][ni],af[mi],bf[ni]);
        }
        if(s+1<nst) sts(cur^1);
        __syncthreads();
    }
#pragma unroll
    for(int mi=0;mi<2;mi++)
#pragma unroll
      for(int ni=0;ni<8;ni++){
        int row=wm*32+mi*16+g, col=n0+wn*64+ni*8+2*t;
        float b0=0.f,b1=0.f;
        if(!ACC){ if(bias1){b0+=bias1[col];b1+=bias1[col+1];}
                  if(bias2){b0+=bias2[col];b1+=bias2[col+1];} }
        if(row<M){float* p=C+(size_t)row*N+col;
            if(ACC){p[0]+=acc[mi][ni][0];p[1]+=acc[mi][ni][1];}
            else   {p[0]=acc[mi][ni][0]+b0;p[1]=acc[mi][ni][1]+b1;}}
        if(row+8<M){float* p=C+(size_t)(row+8)*N+col;
            if(ACC){p[0]+=acc[mi][ni][2];p[1]+=acc[mi][ni][3];}
            else   {p[0]=acc[mi][ni][2]+b0;p[1]=acc[mi][ni][3]+b1;}}
      }
}

// ---- fused score GEMM: part[nt][m] = sum_{n in tile} va[n]*tanh(q[b,n]+enc[m]@Wae[n]) ----
__global__ void __launch_bounds__(256) score_kernel(
    const float* __restrict__ enc,const float* __restrict__ Wae,
    const float* __restrict__ q,const float* __restrict__ va,float* __restrict__ part)
{
    __shared__ float As[2][128][20];
    __shared__ float Bs[2][128][20];
    __shared__ float red[128][2];
    const int tid=threadIdx.x,lane=tid&31,warp=tid>>5;
    const int wm=warp&3,wn=warp>>2,g=lane>>2,t=lane&3;
    const int m0=blockIdx.y*128, n0=blockIdx.x*128;
    float acc[2][8][4];
#pragma unroll
    for(int i=0;i<2;i++)
#pragma unroll
      for(int j=0;j<8;j++)
#pragma unroll
        for(int k=0;k<4;k++) acc[i][j][k]=0.f;
    float4 ra[2],rb[2];
    auto ldg=[&](int k0){
#pragma unroll
        for(int j=0;j<2;j++){int i=tid+256*j,r=i>>2,cb=i&3;
            ra[j]=*reinterpret_cast<const float4*>(enc+(size_t)(m0+r)*1024+k0+cb*4);
            rb[j]=*reinterpret_cast<const float4*>(Wae+(size_t)(n0+r)*1024+k0+cb*4);}
    };
    auto sts=[&](int buf){
#pragma unroll
        for(int j=0;j<2;j++){int i=tid+256*j,r=i>>2,cb=i&3;
            As[buf][r][cb*4+0]=to_tf32(ra[j].x);As[buf][r][cb*4+1]=to_tf32(ra[j].y);
            As[buf][r][cb*4+2]=to_tf32(ra[j].z);As[buf][r][cb*4+3]=to_tf32(ra[j].w);
            Bs[buf][r][cb*4+0]=to_tf32(rb[j].x);Bs[buf][r][cb*4+1]=to_tf32(rb[j].y);
            Bs[buf][r][cb*4+2]=to_tf32(rb[j].z);Bs[buf][r][cb*4+3]=to_tf32(rb[j].w);}
    };
    ldg(0);sts(0);__syncthreads();
    const int nst=1024/16;
    for(int s=0;s<nst;s++){
        const int cur=s&1;
        if(s+1<nst) ldg((s+1)*16);
#pragma unroll
        for(int kk=0;kk<2;kk++){
            const int kb=kk*8;
            uint32_t af[2][4];
#pragma unroll
            for(int mi=0;mi<2;mi++){int mr=wm*32+mi*16;
                af[mi][0]=__float_as_uint(As[cur][mr+g][kb+t]);
                af[mi][1]=__float_as_uint(As[cur][mr+g+8][kb+t]);
                af[mi][2]=__float_as_uint(As[cur][mr+g][kb+t+4]);
                af[mi][3]=__float_as_uint(As[cur][mr+g+8][kb+t+4]);}
            uint32_t bf[8][2];
#pragma unroll
            for(int ni=0;ni<8;ni++){int nr=wn*64+ni*8+g;
                bf[ni][0]=__float_as_uint(Bs[cur][nr][kb+t]);
                bf[ni][1]=__float_as_uint(Bs[cur][nr][kb+t+4]);}
#pragma unroll
            for(int mi=0;mi<2;mi++)
#pragma unroll
                for(int ni=0;ni<8;ni++) mma_tf32(acc[mi][ni],af[mi],bf[ni]);
        }
        if(s+1<nst) sts(cur^1);
        __syncthreads();
    }
    // epilogue: whole CTA covers one batch row b
    const int b=m0>>10;
    const float* qr=q+b*1024;
    float rs[2][2]={{0.f,0.f},{0.f,0.f}};
#pragma unroll
    for(int ni=0;ni<8;ni++){
        int col=n0+wn*64+ni*8+2*t;
        float va0=va[col],va1=va[col+1],q0=qr[col],q1=qr[col+1];
#pragma unroll
        for(int mi=0;mi<2;mi++){
            rs[mi][0]+=va0*fast_tanh(q0+acc[mi][ni][0])+va1*fast_tanh(q1+acc[mi][ni][1]);
            rs[mi][1]+=va0*fast_tanh(q0+acc[mi][ni][2])+va1*fast_tanh(q1+acc[mi][ni][3]);
        }
    }
#pragma unroll
    for(int o=1;o<4;o<<=1)
#pragma unroll
      for(int mi=0;mi<2;mi++){
        rs[mi][0]+=__shfl_xor_sync(0xffffffffu,rs[mi][0],o);
        rs[mi][1]+=__shfl_xor_sync(0xffffffffu,rs[mi][1],o);
      }
    if(t==0)
#pragma unroll
      for(int mi=0;mi<2;mi++){
        red[wm*32+mi*16+g][wn]=rs[mi][0];
        red[wm*32+mi*16+8+g][wn]=rs[mi][1];
      }
    __syncthreads();
    if(tid<128) part[(size_t)blockIdx.x*(NB*NS)+m0+tid]=red[tid][0]+red[tid][1];
}

// ---- softmax over S per batch row; writes attn into d_out ----
__global__ void __launch_bounds__(256) softmax_kernel(const float* __restrict__ part,float* __restrict__ attn){
    __shared__ float sc[NS];
    __shared__ float wred[8];
    const int b=blockIdx.x,tid=threadIdx.x,lane=tid&31,warp=tid>>5;
    float lmax=-1e30f;
    for(int s=tid;s<NS;s+=256){
        float v=0.f;
#pragma unroll
        for(int p=0;p<8;p++) v+=part[(size_t)p*(NB*NS)+b*NS+s];
        sc[s]=v; lmax=fmaxf(lmax,v);
    }
#pragma unroll
    for(int o=16;o>0;o>>=1) lmax=fmaxf(lmax,__shfl_xor_sync(0xffffffffu,lmax,o));
    if(lane==0) wred[warp]=lmax;
    __syncthreads();
    float m=wred[0];
#pragma unroll
    for(int w=1;w<8;w++) m=fmaxf(m,wred[w]);
    __syncthreads();
    float lsum=0.f;
    for(int s=tid;s<NS;s+=256){float e=expf(sc[s]-m);sc[s]=e;lsum+=e;}
#pragma unroll
    for(int o=16;o>0;o>>=1) lsum+=__shfl_xor_sync(0xffffffffu,lsum,o);
    if(lane==0) wred[warp]=lsum;
    __syncthreads();
    float tot=0.f;
#pragma unroll
    for(int w=0;w<8;w++) tot+=wred[w];
    const float inv=1.f/tot;
    for(int s=tid;s<NS;s+=256) attn[b*NS+s]=sc[s]*inv;
}

// ---- context[b,e] = sum_s attn[b,s]*enc[b,s,e]; writes g_x[b][1024+e] ----
__global__ void __launch_bounds__(128) context_kernel(const float* __restrict__ attn,
    const float* __restrict__ enc,float* __restrict__ x){
    __shared__ float aw[NS];
    const int b=blockIdx.x,e=blockIdx.y*128+threadIdx.x;
    for(int s=threadIdx.x;s<NS;s+=128) aw[s]=attn[b*NS+s];
    __syncthreads();
    float acc=0.f;
    const float* ep=enc+(size_t)b*NS*1024+e;
    for(int s=0;s<NS;s++) acc+=aw[s]*ep[(size_t)s*1024];
    x[b*2048+1024+e]=acc;
}

// ---- LSTM pointwise: gates[b][4096] -> h,c ----
__global__ void __launch_bounds__(256) lstm_kernel(const float* __restrict__ gates,
    const float* __restrict__ cprev,float* __restrict__ hout,float* __restrict__ cout,
    float* __restrict__ hscratch){
    const int b=blockIdx.x;
    for(int j=threadIdx.x;j<1024;j+=256){
        float gi=gates[b*4096+j], gf=gates[b*4096+1024+j];
        float gg=gates[b*4096+2048+j], go=gates[b*4096+3072+j];
        float c=sigf(gf)*cprev[b*1024+j]+sigf(gi)*tanhf(gg);
        float h=sigf(go)*tanhf(c);
        hout[b*1024+j]=h; cout[b*1024+j]=c; hscratch[b*1024+j]=h;
    }
}

extern "C" void kernel_launch(void* const* d_in,const int* in_sizes,int n_in,
                              void* d_out,int out_size){
    const int*   step = (const int*)  d_in[0];
    const float* h0   = (const float*)d_in[1];   // [2,64,1024]
    const float* c0   = (const float*)d_in[2];
    const float* enc  = (const float*)d_in[3];   // [64,1024,1024]
    const float* emb  = (const float*)d_in[4];
    const float* Wah  = (const float*)d_in[5];
    const float* bah  = (const float*)d_in[6];
    const float* Wae  = (const float*)d_in[7];
    const float* bae  = (const float*)d_in[8];
    const float* va   = (const float*)d_in[9];
    const float* Wih0 = (const float*)d_in[11];
    const float* Whh0 = (const float*)d_in[12];
    const float* bih0 = (const float*)d_in[13];
    const float* bhh0 = (const float*)d_in[14];
    const float* Wih1 = (const float*)d_in[15];
    const float* Whh1 = (const float*)d_in[16];
    const float* bih1 = (const float*)d_in[17];
    const float* bhh1 = (const float*)d_in[18];
    const float* Wout = (const float*)d_in[19];
    const float* bout = (const float*)d_in[20];
    float* out=(float*)d_out;

    float *q,*part,*x,*gates,*h1,*h2;
    cudaGetSymbolAddress((void**)&q,g_q);
    cudaGetSymbolAddress((void**)&part,g_part);
    cudaGetSymbolAddress((void**)&x,g_x);
    cudaGetSymbolAddress((void**)&gates,g_gates);
    cudaGetSymbolAddress((void**)&h1,g_h1);
    cudaGetSymbolAddress((void**)&h2,g_h2);

    embed_kernel<<<64,256>>>(step,emb,x);
    // q = h0[-1]@Wah^T + bah + bae
    gemm_tf32_kernel<false><<<8,128>>>(h0+64*1024,Wah,q,64,1024,1024,bah,bae);
    // fused attention scores
    score_kernel<<<dim3(8,512),256>>>(enc,Wae,q,va,part);
    softmax_kernel<<<64,256>>>(part,out+OUT_ATT);
    context_kernel<<<dim3(64,8),128>>>(out+OUT_ATT,enc,x);
    // layer 0 gates
    gemm_tf32_kernel<false><<<32,128>>>(x,Wih0,gates,64,4096,2048,bih0,bhh0);
    gemm_tf32_kernel<true ><<<32,128>>>(h0,Whh0,gates,64,4096,1024,nullptr,nullptr);
    lstm_kernel<<<64,256>>>(gates,c0,out+OUT_H,out+OUT_C,h1);
    // layer 1 gates
    gemm_tf32_kernel<false><<<32,128>>>(h1,Wih1,gates,64,4096,1024,bih1,bhh1);
    gemm_tf32_kernel<true ><<<32,128>>>(h0+64*1024,Whh1,gates,64,4096,1024,nullptr,nullptr);
    lstm_kernel<<<64,256>>>(gates,c0+64*1024,out+OUT_H+64*1024,out+OUT_C+64*1024,h2);
    // logits
    gemm_tf32_kernel<false><<<250,128>>>(h2,Wout,out,64,32000,1024,bout,nullptr);
}

// round 4
// speedup vs baseline: 1.8172x; 1.8172x over previous
#include <cuda_runtime.h>
#include <cuda_bf16.h>
#include <stdint.h>
#include <math.h>

#define NB 64
#define NS 1024
#define NV 32000
#define NH 1024
// out: logits[64*32000] | h_new[2*64*1024] | c_new[2*64*1024] | attn[64*1024]
#define OUT_H   (NB*NV)
#define OUT_C   (OUT_H + 2*NB*NH)
#define OUT_ATT (OUT_C + 2*NB*NH)

__device__ float g_q[NB*1024];
__device__ float g_part[8*NB*NS];
__device__ float g_x[NB*2048];
__device__ float g_gates[NB*4096];
__device__ float g_h1[NB*NH];
__device__ float g_h2[NB*NH];

__device__ __forceinline__ float fast_tanh(float x){float y;asm("tanh.approx.f32 %0,%1;":"=f"(y):"f"(x));return y;}
__device__ __forceinline__ float to_tf32(float x){uint32_t u;asm("cvt.rna.tf32.f32 %0,%1;":"=r"(u):"f"(x));return __uint_as_float(u);}
__device__ __forceinline__ float sigf(float x){return 1.f/(1.f+expf(-x));}

__device__ __forceinline__ void mma_tf32(float* c,const uint32_t* a,const uint32_t* b){
    asm volatile("mma.sync.aligned.m16n8k8.row.col.f32.tf32.tf32.f32 "
        "{%0,%1,%2,%3},{%4,%5,%6,%7},{%8,%9},{%0,%1,%2,%3};\n"
        : "+f"(c[0]),"+f"(c[1]),"+f"(c[2]),"+f"(c[3])
        : "r"(a[0]),"r"(a[1]),"r"(a[2]),"r"(a[3]),"r"(b[0]),"r"(b[1]));
}

// ---- embed: g_x[b][0:1024] = emb[step[b]] ----
__global__ void embed_kernel(const int* __restrict__ step,const float* __restrict__ emb,float* __restrict__ x){
    int b=blockIdx.x; int idx=step[b];
    for(int j=threadIdx.x;j<1024;j+=256) x[b*2048+j]=emb[(size_t)idx*1024+j];
}

// ===========================================================================
// Fused attention-score GEMM (the heavy one, legacy tf32 mma):
//   part[nt][m] = sum_{n in 128-tile nt} va[n]*tanh(q[b(m),n] + enc[m,:]@Wae[n,:])
// CTA 128x128, 4 warps in 2x2 grid, warp tile 64x64, K-chunk 16, double buffer.
// ===========================================================================
__global__ void __launch_bounds__(128,2) score_kernel(
    const float* __restrict__ enc,const float* __restrict__ Wae,
    const float* __restrict__ q,const float* __restrict__ va,float* __restrict__ part)
{
    __shared__ float As[2][128][20];
    __shared__ float Bs[2][128][20];
    __shared__ float red[128][2];
    __shared__ float2 qa[128];

    const int tid=threadIdx.x,lane=tid&31,warp=tid>>5;
    const int wm=warp&1,wn=warp>>1;         // 2 (M) x 2 (N)
    const int g=lane>>2,t=lane&3;
    const int m0=blockIdx.y*128, n0=blockIdx.x*128;
    const int b=blockIdx.y>>3;              // 8 m-tiles per batch row

    qa[tid]=make_float2(q[b*1024+n0+tid], va[n0+tid]);

    float acc[4][8][4];
#pragma unroll
    for(int i=0;i<4;i++)
#pragma unroll
      for(int j=0;j<8;j++)
#pragma unroll
        for(int k=0;k<4;k++) acc[i][j][k]=0.f;

    float4 ra[4],rb[4];
    auto ldg=[&](int k0){
#pragma unroll
        for(int j=0;j<4;j++){int i=tid+128*j,r=i>>2,cb=i&3;
            ra[j]=*reinterpret_cast<const float4*>(enc+(size_t)(m0+r)*1024+k0+cb*4);
            rb[j]=*reinterpret_cast<const float4*>(Wae+(size_t)(n0+r)*1024+k0+cb*4);}
    };
    auto sts=[&](int buf){
#pragma unroll
        for(int j=0;j<4;j++){int i=tid+128*j,r=i>>2,cb=i&3;
            As[buf][r][cb*4+0]=to_tf32(ra[j].x);As[buf][r][cb*4+1]=to_tf32(ra[j].y);
            As[buf][r][cb*4+2]=to_tf32(ra[j].z);As[buf][r][cb*4+3]=to_tf32(ra[j].w);
            Bs[buf][r][cb*4+0]=to_tf32(rb[j].x);Bs[buf][r][cb*4+1]=to_tf32(rb[j].y);
            Bs[buf][r][cb*4+2]=to_tf32(rb[j].z);Bs[buf][r][cb*4+3]=to_tf32(rb[j].w);}
    };

    ldg(0);sts(0);__syncthreads();
    const int nst=1024/16;
    for(int s=0;s<nst;s++){
        const int cur=s&1;
        if(s+1<nst) ldg((s+1)*16);
#pragma unroll
        for(int kk=0;kk<2;kk++){
            const int kb=kk*8;
            uint32_t af[4][4];
#pragma unroll
            for(int mi=0;mi<4;mi++){int mr=wm*64+mi*16;
                af[mi][0]=__float_as_uint(As[cur][mr+g][kb+t]);
                af[mi][1]=__float_as_uint(As[cur][mr+g+8][kb+t]);
                af[mi][2]=__float_as_uint(As[cur][mr+g][kb+t+4]);
                af[mi][3]=__float_as_uint(As[cur][mr+g+8][kb+t+4]);}
            uint32_t bf[8][2];
#pragma unroll
            for(int ni=0;ni<8;ni++){int nr=wn*64+ni*8+g;
                bf[ni][0]=__float_as_uint(Bs[cur][nr][kb+t]);
                bf[ni][1]=__float_as_uint(Bs[cur][nr][kb+t+4]);}
#pragma unroll
            for(int mi=0;mi<4;mi++)
#pragma unroll
                for(int ni=0;ni<8;ni++) mma_tf32(acc[mi][ni],af[mi],bf[ni]);
        }
        if(s+1<nst) sts(cur^1);
        __syncthreads();
    }

    // epilogue: va*tanh(q + k), reduce over this CTA's 128 n-columns
    float rs[4][2];
#pragma unroll
    for(int mi=0;mi<4;mi++){rs[mi][0]=0.f;rs[mi][1]=0.f;}
#pragma unroll
    for(int ni=0;ni<8;ni++){
        int col=wn*64+ni*8+2*t;
        float2 qa0=qa[col], qa1=qa[col+1];
#pragma unroll
        for(int mi=0;mi<4;mi++){
            rs[mi][0]+=qa0.y*fast_tanh(qa0.x+acc[mi][ni][0])+qa1.y*fast_tanh(qa1.x+acc[mi][ni][1]);
            rs[mi][1]+=qa0.y*fast_tanh(qa0.x+acc[mi][ni][2])+qa1.y*fast_tanh(qa1.x+acc[mi][ni][3]);
        }
    }
#pragma unroll
    for(int o=1;o<4;o<<=1)
#pragma unroll
      for(int mi=0;mi<4;mi++){
        rs[mi][0]+=__shfl_xor_sync(0xffffffffu,rs[mi][0],o);
        rs[mi][1]+=__shfl_xor_sync(0xffffffffu,rs[mi][1],o);
      }
    if(t==0)
#pragma unroll
      for(int mi=0;mi<4;mi++){
        red[wm*64+mi*16+g][wn]=rs[mi][0];
        red[wm*64+mi*16+8+g][wn]=rs[mi][1];
      }
    __syncthreads();
    part[(size_t)blockIdx.x*(NB*NS)+m0+tid]=red[tid][0]+red[tid][1];
}

// ---- generic skinny GEMM: C[M<=64,N] = A[M,K]@B[N,K]^T (+bias or +=) ----
template<bool ACC>
__global__ void __launch_bounds__(128) gemm_tf32_kernel(
    const float* __restrict__ A,const float* __restrict__ Bm,float* __restrict__ C,
    int M,int N,int K,const float* __restrict__ bias1,const float* __restrict__ bias2)
{
    __shared__ float As[2][64][20];
    __shared__ float Bs[2][128][20];
    const int tid=threadIdx.x,lane=tid&31,warp=tid>>5;
    const int wm=warp&1,wn=warp>>1,g=lane>>2,t=lane&3;
    const int n0=blockIdx.x*128;
    float acc[2][8][4];
#pragma unroll
    for(int i=0;i<2;i++)
#pragma unroll
      for(int j=0;j<8;j++)
#pragma unroll
        for(int k=0;k<4;k++) acc[i][j][k]=0.f;
    float4 ra[2],rb[4];
    auto ldg=[&](int k0){
#pragma unroll
        for(int j=0;j<2;j++){int i=tid+128*j,r=i>>2,cb=i&3;
            ra[j]=*reinterpret_cast<const float4*>(A+(size_t)r*K+k0+cb*4);}
#pragma unroll
        for(int j=0;j<4;j++){int i=tid+128*j,r=i>>2,cb=i&3;
            rb[j]=*reinterpret_cast<const float4*>(Bm+(size_t)(n0+r)*K+k0+cb*4);}
    };
    auto sts=[&](int buf){
#pragma unroll
        for(int j=0;j<2;j++){int i=tid+128*j,r=i>>2,cb=i&3;
            As[buf][r][cb*4+0]=to_tf32(ra[j].x);As[buf][r][cb*4+1]=to_tf32(ra[j].y);
            As[buf][r][cb*4+2]=to_tf32(ra[j].z);As[buf][r][cb*4+3]=to_tf32(ra[j].w);}
#pragma unroll
        for(int j=0;j<4;j++){int i=tid+128*j,r=i>>2,cb=i&3;
            Bs[buf][r][cb*4+0]=to_tf32(rb[j].x);Bs[buf][r][cb*4+1]=to_tf32(rb[j].y);
            Bs[buf][r][cb*4+2]=to_tf32(rb[j].z);Bs[buf][r][cb*4+3]=to_tf32(rb[j].w);}
    };
    ldg(0);sts(0);__syncthreads();
    const int nst=K/16;
    for(int s=0;s<nst;s++){
        const int cur=s&1;
        if(s+1<nst) ldg((s+1)*16);
#pragma unroll
        for(int kk=0;kk<2;kk++){
            const int kb=kk*8;
            uint32_t af[2][4];
#pragma unroll
            for(int mi=0;mi<2;mi++){int mr=wm*32+mi*16;
                af[mi][0]=__float_as_uint(As[cur][mr+g][kb+t]);
                af[mi][1]=__float_as_uint(As[cur][mr+g+8][kb+t]);
                af[mi][2]=__float_as_uint(As[cur][mr+g][kb+t+4]);
                af[mi][3]=__float_as_uint(As[cur][mr+g+8][kb+t+4]);}
            uint32_t bf[8][2];
#pragma unroll
            for(int ni=0;ni<8;ni++){int nr=wn*64+ni*8+g;
                bf[ni][0]=__float_as_uint(Bs[cur][nr][kb+t]);
                bf[ni][1]=__float_as_uint(Bs[cur][nr][kb+t+4]);}
#pragma unroll
            for(int mi=0;mi<2;mi++)
#pragma unroll
                for(int ni=0;ni<8;ni++) mma_tf32(acc[mi][ni],af[mi],bf[ni]);
        }
        if(s+1<nst) sts(cur^1);
        __syncthreads();
    }
#pragma unroll
    for(int mi=0;mi<2;mi++)
#pragma unroll
      for(int ni=0;ni<8;ni++){
        int row=wm*32+mi*16+g, col=n0+wn*64+ni*8+2*t;
        float b0=0.f,b1=0.f;
        if(!ACC){ if(bias1){b0+=bias1[col];b1+=bias1[col+1];}
                  if(bias2){b0+=bias2[col];b1+=bias2[col+1];} }
        if(row<M){float* p=C+(size_t)row*N+col;
            if(ACC){p[0]+=acc[mi][ni][0];p[1]+=acc[mi][ni][1];}
            else   {p[0]=acc[mi][ni][0]+b0;p[1]=acc[mi][ni][1]+b1;}}
        if(row+8<M){float* p=C+(size_t)(row+8)*N+col;
            if(ACC){p[0]+=acc[mi][ni][2];p[1]+=acc[mi][ni][3];}
            else   {p[0]=acc[mi][ni][2]+b0;p[1]=acc[mi][ni][3]+b1;}}
      }
}

// ---- softmax over S per batch row (8 partial slabs) ----
__global__ void __launch_bounds__(256) softmax_kernel(const float* __restrict__ part,float* __restrict__ attn){
    __shared__ float sc[NS];
    __shared__ float wred[8];
    const int b=blockIdx.x,tid=threadIdx.x,lane=tid&31,warp=tid>>5;
    float lmax=-1e30f;
    for(int s=tid;s<NS;s+=256){
        float v=0.f;
#pragma unroll
        for(int p=0;p<8;p++) v+=part[(size_t)p*(NB*NS)+b*NS+s];
        sc[s]=v; lmax=fmaxf(lmax,v);
    }
#pragma unroll
    for(int o=16;o>0;o>>=1) lmax=fmaxf(lmax,__shfl_xor_sync(0xffffffffu,lmax,o));
    if(lane==0) wred[warp]=lmax;
    __syncthreads();
    float m=wred[0];
#pragma unroll
    for(int w=1;w<8;w++) m=fmaxf(m,wred[w]);
    __syncthreads();
    float lsum=0.f;
    for(int s=tid;s<NS;s+=256){float e=expf(sc[s]-m);sc[s]=e;lsum+=e;}
#pragma unroll
    for(int o=16;o>0;o>>=1) lsum+=__shfl_xor_sync(0xffffffffu,lsum,o);
    if(lane==0) wred[warp]=lsum;
    __syncthreads();
    float tot=0.f;
#pragma unroll
    for(int w=0;w<8;w++) tot+=wred[w];
    const float inv=1.f/tot;
    for(int s=tid;s<NS;s+=256) attn[b*NS+s]=sc[s]*inv;
}

// ---- context[b,e] = sum_s attn[b,s]*enc[b,s,e] ----
__global__ void __launch_bounds__(128) context_kernel(const float* __restrict__ attn,
    const float* __restrict__ enc,float* __restrict__ x){
    __shared__ float aw[NS];
    const int b=blockIdx.x,e=blockIdx.y*128+threadIdx.x;
    for(int s=threadIdx.x;s<NS;s+=128) aw[s]=attn[b*NS+s];
    __syncthreads();
    float a0=0.f,a1=0.f,a2=0.f,a3=0.f;
    const float* ep=enc+(size_t)b*NS*1024+e;
    for(int s=0;s<NS;s+=4){
        a0+=aw[s+0]*ep[(size_t)(s+0)*1024];
        a1+=aw[s+1]*ep[(size_t)(s+1)*1024];
        a2+=aw[s+2]*ep[(size_t)(s+2)*1024];
        a3+=aw[s+3]*ep[(size_t)(s+3)*1024];
    }
    x[b*2048+1024+e]=(a0+a1)+(a2+a3);
}

// ---- LSTM pointwise ----
__global__ void __launch_bounds__(256) lstm_kernel(const float* __restrict__ gates,
    const float* __restrict__ cprev,float* __restrict__ hout,float* __restrict__ cout,
    float* __restrict__ hscratch){
    const int b=blockIdx.x;
    for(int j=threadIdx.x;j<1024;j+=256){
        float gi=gates[b*4096+j], gf=gates[b*4096+1024+j];
        float gg=gates[b*4096+2048+j], go=gates[b*4096+3072+j];
        float c=sigf(gf)*cprev[b*1024+j]+sigf(gi)*tanhf(gg);
        float h=sigf(go)*tanhf(c);
        hout[b*1024+j]=h; cout[b*1024+j]=c; hscratch[b*1024+j]=h;
    }
}

extern "C" void kernel_launch(void* const* d_in,const int* in_sizes,int n_in,
                              void* d_out,int out_size){
    const int*   step = (const int*)  d_in[0];
    const float* h0   = (const float*)d_in[1];
    const float* c0   = (const float*)d_in[2];
    const float* enc  = (const float*)d_in[3];
    const float* emb  = (const float*)d_in[4];
    const float* Wah  = (const float*)d_in[5];
    const float* bah  = (const float*)d_in[6];
    const float* Wae  = (const float*)d_in[7];
    const float* bae  = (const float*)d_in[8];
    const float* va   = (const float*)d_in[9];
    const float* Wih0 = (const float*)d_in[11];
    const float* Whh0 = (const float*)d_in[12];
    const float* bih0 = (const float*)d_in[13];
    const float* bhh0 = (const float*)d_in[14];
    const float* Wih1 = (const float*)d_in[15];
    const float* Whh1 = (const float*)d_in[16];
    const float* bih1 = (const float*)d_in[17];
    const float* bhh1 = (const float*)d_in[18];
    const float* Wout = (const float*)d_in[19];
    const float* bout = (const float*)d_in[20];
    float* out=(float*)d_out;

    float *q,*part,*x,*gates,*h1,*h2;
    cudaGetSymbolAddress((void**)&q,g_q);
    cudaGetSymbolAddress((void**)&part,g_part);
    cudaGetSymbolAddress((void**)&x,g_x);
    cudaGetSymbolAddress((void**)&gates,g_gates);
    cudaGetSymbolAddress((void**)&h1,g_h1);
    cudaGetSymbolAddress((void**)&h2,g_h2);

    embed_kernel<<<64,256>>>(step,emb,x);
    // q = h0[-1]@Wah^T + bah + bae
    gemm_tf32_kernel<false><<<8,128>>>(h0+64*1024,Wah,q,64,1024,1024,bah,bae);
    // fused attention scores
    score_kernel<<<dim3(8,512),128>>>(enc,Wae,q,va,part);
    softmax_kernel<<<64,256>>>(part,out+OUT_ATT);
    context_kernel<<<dim3(64,8),128>>>(out+OUT_ATT,enc,x);
    // layer 0
    gemm_tf32_kernel<false><<<32,128>>>(x,Wih0,gates,64,4096,2048,bih0,bhh0);
    gemm_tf32_kernel<true ><<<32,128>>>(h0,Whh0,gates,64,4096,1024,nullptr,nullptr);
    lstm_kernel<<<64,256>>>(gates,c0,out+OUT_H,out+OUT_C,h1);
    // layer 1
    gemm_tf32_kernel<false><<<32,128>>>(h1,Wih1,gates,64,4096,1024,bih1,bhh1);
    gemm_tf32_kernel<true ><<<32,128>>>(h0+64*1024,Whh1,gates,64,4096,1024,nullptr,nullptr);
    lstm_kernel<<<64,256>>>(gates,c0+64*1024,out+OUT_H+64*1024,out+OUT_C+64*1024,h2);
    // logits
    gemm_tf32_kernel<false><<<250,128>>>(h2,Wout,out,64,32000,1024,bout,nullptr);
}

// round 6
// speedup vs baseline: 2.2941x; 1.2625x over previous
#include <cuda_runtime.h>
#include <cuda_bf16.h>
#include <stdint.h>
#include <math.h>

#define NB 64
#define NS 1024
#define NV 32000
#define NH 1024
// out: logits[64*32000] | h_new[2*64*1024] | c_new[2*64*1024] | attn[64*1024]
#define OUT_H   (NB*NV)
#define OUT_C   (OUT_H + 2*NB*NH)
#define OUT_ATT (OUT_C + 2*NB*NH)

__device__ float g_q[NB*1024];
__device__ float g_part[8*NB*NS];
__device__ float g_x[NB*2048];
__device__ float g_gates[NB*4096];
__device__ float g_h1[NB*NH];
__device__ float g_h2[NB*NH];

__device__ __forceinline__ float fast_tanh(float x){float y;asm("tanh.approx.f32 %0,%1;":"=f"(y):"f"(x));return y;}
__device__ __forceinline__ float to_tf32(float x){uint32_t u;asm("cvt.rna.tf32.f32 %0,%1;":"=r"(u):"f"(x));return __uint_as_float(u);}
__device__ __forceinline__ float sigf(float x){return 1.f/(1.f+expf(-x));}

__device__ __forceinline__ uint32_t smem_u32(const void* p){
    uint32_t a; asm("{ .reg .u64 t; cvta.to.shared.u64 t, %1; cvt.u32.u64 %0, t; }":"=r"(a):"l"(p)); return a;
}

__device__ __forceinline__ void mma_tf32(float* c,const uint32_t* a,const uint32_t* b){
    asm volatile("mma.sync.aligned.m16n8k8.row.col.f32.tf32.tf32.f32 "
        "{%0,%1,%2,%3},{%4,%5,%6,%7},{%8,%9},{%0,%1,%2,%3};\n"
        : "+f"(c[0]),"+f"(c[1]),"+f"(c[2]),"+f"(c[3])
        : "r"(a[0]),"r"(a[1]),"r"(a[2]),"r"(a[3]),"r"(b[0]),"r"(b[1]));
}
__device__ __forceinline__ void mma_bf16(float* c,const uint32_t* a,const uint32_t* b){
    asm volatile("mma.sync.aligned.m16n8k16.row.col.f32.bf16.bf16.f32 "
        "{%0,%1,%2,%3},{%4,%5,%6,%7},{%8,%9},{%0,%1,%2,%3};\n"
        : "+f"(c[0]),"+f"(c[1]),"+f"(c[2]),"+f"(c[3])
        : "r"(a[0]),"r"(a[1]),"r"(a[2]),"r"(a[3]),"r"(b[0]),"r"(b[1]));
}
#define LDSM4(r0,r1,r2,r3,addr) \
    asm volatile("ldmatrix.sync.aligned.m8n8.x4.shared.b16 {%0,%1,%2,%3},[%4];" \
        : "=r"(r0),"=r"(r1),"=r"(r2),"=r"(r3) : "r"(addr))

// ---- embed: g_x[b][0:1024] = emb[step[b]] ----
__global__ void embed_kernel(const int* __restrict__ step,const float* __restrict__ emb,float* __restrict__ x){
    int b=blockIdx.x; int idx=step[b];
    for(int j=threadIdx.x;j<1024;j+=256) x[b*2048+j]=emb[(size_t)idx*1024+j];
}

// ===========================================================================
// Fused attention-score GEMM (bf16 mma + ldmatrix):
//   part[nt][m] = sum_{n in 128-tile nt} va[n]*tanh(q[b(m),n] + enc[m,:]@Wae[n,:])
// CTA 128x128, 4 warps (2x2), warp tile 64x64, K-chunk 16, double buffer.
// Smem rows: 24 bf16 (48B) -> conflict-free ldmatrix ((3r+c)%8 permutation).
// ===========================================================================
__global__ void __launch_bounds__(128,2) score_kernel(
    const float* __restrict__ enc,const float* __restrict__ Wae,
    const float* __restrict__ q,const float* __restrict__ va,float* __restrict__ part)
{
    __shared__ __align__(16) __nv_bfloat16 As[2][128][24];
    __shared__ __align__(16) __nv_bfloat16 Bs[2][128][24];
    __shared__ float red[128][2];
    __shared__ float2 qa[128];

    const int tid=threadIdx.x,lane=tid&31,warp=tid>>5;
    const int wm=warp&1,wn=warp>>1;         // 2 (M) x 2 (N)
    const int g=lane>>2,t=lane&3;
    const int m0=blockIdx.y*128, n0=blockIdx.x*128;
    const int b=blockIdx.y>>3;              // 8 m-tiles per batch row

    qa[tid]=make_float2(q[b*1024+n0+tid], va[n0+tid]);

    const uint32_t aB=smem_u32(&As[0][0][0]);
    const uint32_t bB=smem_u32(&Bs[0][0][0]);
    // ldmatrix per-lane base addresses
    const uint32_t aAdr = aB + (uint32_t)((wm*64+(lane&15))*48 + (lane>>4)*16);
    const uint32_t bAdr = bB + (uint32_t)((wn*64+(lane&7)+((lane&16)?8:0))*48 + ((lane>>3)&1)*16);

    float acc[4][8][4];
#pragma unroll
    for(int i=0;i<4;i++)
#pragma unroll
      for(int j=0;j<8;j++)
#pragma unroll
        for(int k=0;k<4;k++) acc[i][j][k]=0.f;

    float4 ra[4],rb[4];
    auto ldg=[&](int k0){
#pragma unroll
        for(int j=0;j<4;j++){int i=tid+128*j,r=i>>2,cb=i&3;
            ra[j]=*reinterpret_cast<const float4*>(enc+(size_t)(m0+r)*1024+k0+cb*4);
            rb[j]=*reinterpret_cast<const float4*>(Wae+(size_t)(n0+r)*1024+k0+cb*4);}
    };
    auto sts=[&](int buf){
#pragma unroll
        for(int j=0;j<4;j++){int i=tid+128*j,r=i>>2,cb=i&3;
            __nv_bfloat162 lo=__floats2bfloat162_rn(ra[j].x,ra[j].y);
            __nv_bfloat162 hi=__floats2bfloat162_rn(ra[j].z,ra[j].w);
            uint2 v; v.x=*reinterpret_cast<uint32_t*>(&lo); v.y=*reinterpret_cast<uint32_t*>(&hi);
            *reinterpret_cast<uint2*>(&As[buf][r][cb*4])=v;
            lo=__floats2bfloat162_rn(rb[j].x,rb[j].y);
            hi=__floats2bfloat162_rn(rb[j].z,rb[j].w);
            v.x=*reinterpret_cast<uint32_t*>(&lo); v.y=*reinterpret_cast<uint32_t*>(&hi);
            *reinterpret_cast<uint2*>(&Bs[buf][r][cb*4])=v;}
    };

    ldg(0);sts(0);__syncthreads();
    const int nst=1024/16;
    for(int s=0;s<nst;s++){
        const int cur=s&1;
        const uint32_t bufOff=(uint32_t)cur*128*48;
        if(s+1<nst) ldg((s+1)*16);
        uint32_t af[4][4];
#pragma unroll
        for(int mi=0;mi<4;mi++)
            LDSM4(af[mi][0],af[mi][1],af[mi][2],af[mi][3], aAdr+bufOff+(uint32_t)mi*768);
        uint32_t bf[8][2];
#pragma unroll
        for(int p=0;p<4;p++)
            LDSM4(bf[2*p][0],bf[2*p][1],bf[2*p+1][0],bf[2*p+1][1], bAdr+bufOff+(uint32_t)p*768);
#pragma unroll
        for(int mi=0;mi<4;mi++)
#pragma unroll
            for(int ni=0;ni<8;ni++) mma_bf16(acc[mi][ni],af[mi],bf[ni]);
        if(s+1<nst) sts(cur^1);
        __syncthreads();
    }

    // epilogue: va*tanh(q + k), reduce over this CTA's 128 n-columns
    float rs[4][2];
#pragma unroll
    for(int mi=0;mi<4;mi++){rs[mi][0]=0.f;rs[mi][1]=0.f;}
#pragma unroll
    for(int ni=0;ni<8;ni++){
        int col=wn*64+ni*8+2*t;
        float2 qa0=qa[col], qa1=qa[col+1];
#pragma unroll
        for(int mi=0;mi<4;mi++){
            rs[mi][0]+=qa0.y*fast_tanh(qa0.x+acc[mi][ni][0])+qa1.y*fast_tanh(qa1.x+acc[mi][ni][1]);
            rs[mi][1]+=qa0.y*fast_tanh(qa0.x+acc[mi][ni][2])+qa1.y*fast_tanh(qa1.x+acc[mi][ni][3]);
        }
    }
#pragma unroll
    for(int o=1;o<4;o<<=1)
#pragma unroll
      for(int mi=0;mi<4;mi++){
        rs[mi][0]+=__shfl_xor_sync(0xffffffffu,rs[mi][0],o);
        rs[mi][1]+=__shfl_xor_sync(0xffffffffu,rs[mi][1],o);
      }
    if(t==0)
#pragma unroll
      for(int mi=0;mi<4;mi++){
        red[wm*64+mi*16+g][wn]=rs[mi][0];
        red[wm*64+mi*16+8+g][wn]=rs[mi][1];
      }
    __syncthreads();
    part[(size_t)blockIdx.x*(NB*NS)+m0+tid]=red[tid][0]+red[tid][1];
}

// ---- generic skinny GEMM: C[M<=64,N] = A[M,K]@B[N,K]^T (+bias or +=), tf32 ----
template<bool ACC>
__global__ void __launch_bounds__(128) gemm_tf32_kernel(
    const float* __restrict__ A,const float* __restrict__ Bm,float* __restrict__ C,
    int M,int N,int K,const float* __restrict__ bias1,const float* __restrict__ bias2)
{
    __shared__ float As[2][64][20];
    __shared__ float Bs[2][128][20];
    const int tid=threadIdx.x,lane=tid&31,warp=tid>>5;
    const int wm=warp&1,wn=warp>>1,g=lane>>2,t=lane&3;
    const int n0=blockIdx.x*128;
    float acc[2][8][4];
#pragma unroll
    for(int i=0;i<2;i++)
#pragma unroll
      for(int j=0;j<8;j++)
#pragma unroll
        for(int k=0;k<4;k++) acc[i][j][k]=0.f;
    float4 ra[2],rb[4];
    auto ldg=[&](int k0){
#pragma unroll
        for(int j=0;j<2;j++){int i=tid+128*j,r=i>>2,cb=i&3;
            ra[j]=*reinterpret_cast<const float4*>(A+(size_t)r*K+k0+cb*4);}
#pragma unroll
        for(int j=0;j<4;j++){int i=tid+128*j,r=i>>2,cb=i&3;
            rb[j]=*reinterpret_cast<const float4*>(Bm+(size_t)(n0+r)*K+k0+cb*4);}
    };
    auto sts=[&](int buf){
#pragma unroll
        for(int j=0;j<2;j++){int i=tid+128*j,r=i>>2,cb=i&3;
            As[buf][r][cb*4+0]=to_tf32(ra[j].x);As[buf][r][cb*4+1]=to_tf32(ra[j].y);
            As[buf][r][cb*4+2]=to_tf32(ra[j].z);As[buf][r][cb*4+3]=to_tf32(ra[j].w);}
#pragma unroll
        for(int j=0;j<4;j++){int i=tid+128*j,r=i>>2,cb=i&3;
            Bs[buf][r][cb*4+0]=to_tf32(rb[j].x);Bs[buf][r][cb*4+1]=to_tf32(rb[j].y);
            Bs[buf][r][cb*4+2]=to_tf32(rb[j].z);Bs[buf][r][cb*4+3]=to_tf32(rb[j].w);}
    };
    ldg(0);sts(0);__syncthreads();
    const int nst=K/16;
    for(int s=0;s<nst;s++){
        const int cur=s&1;
        if(s+1<nst) ldg((s+1)*16);
#pragma unroll
        for(int kk=0;kk<2;kk++){
            const int kb=kk*8;
            uint32_t af[2][4];
#pragma unroll
            for(int mi=0;mi<2;mi++){int mr=wm*32+mi*16;
                af[mi][0]=__float_as_uint(As[cur][mr+g][kb+t]);
                af[mi][1]=__float_as_uint(As[cur][mr+g+8][kb+t]);
                af[mi][2]=__float_as_uint(As[cur][mr+g][kb+t+4]);
                af[mi][3]=__float_as_uint(As[cur][mr+g+8][kb+t+4]);}
            uint32_t bf[8][2];
#pragma unroll
            for(int ni=0;ni<8;ni++){int nr=wn*64+ni*8+g;
                bf[ni][0]=__float_as_uint(Bs[cur][nr][kb+t]);
                bf[ni][1]=__float_as_uint(Bs[cur][nr][kb+t+4]);}
#pragma unroll
            for(int mi=0;mi<2;mi++)
#pragma unroll
                for(int ni=0;ni<8;ni++) mma_tf32(acc[mi][ni],af[mi],bf[ni]);
        }
        if(s+1<nst) sts(cur^1);
        __syncthreads();
    }
#pragma unroll
    for(int mi=0;mi<2;mi++)
#pragma unroll
      for(int ni=0;ni<8;ni++){
        int row=wm*32+mi*16+g, col=n0+wn*64+ni*8+2*t;
        float b0=0.f,b1=0.f;
        if(!ACC){ if(bias1){b0+=bias1[col];b1+=bias1[col+1];}
                  if(bias2){b0+=bias2[col];b1+=bias2[col+1];} }
        if(row<M){float* p=C+(size_t)row*N+col;
            if(ACC){p[0]+=acc[mi][ni][0];p[1]+=acc[mi][ni][1];}
            else   {p[0]=acc[mi][ni][0]+b0;p[1]=acc[mi][ni][1]+b1;}}
        if(row+8<M){float* p=C+(size_t)(row+8)*N+col;
            if(ACC){p[0]+=acc[mi][ni][2];p[1]+=acc[mi][ni][3];}
            else   {p[0]=acc[mi][ni][2]+b0;p[1]=acc[mi][ni][3]+b1;}}
      }
}

// ---- softmax over S per batch row (8 partial slabs) ----
__global__ void __launch_bounds__(256) softmax_kernel(const float* __restrict__ part,float* __restrict__ attn){
    __shared__ float sc[NS];
    __shared__ float wred[8];
    const int b=blockIdx.x,tid=threadIdx.x,lane=tid&31,warp=tid>>5;
    float lmax=-1e30f;
    for(int s=tid;s<NS;s+=256){
        float v=0.f;
#pragma unroll
        for(int p=0;p<8;p++) v+=part[(size_t)p*(NB*NS)+b*NS+s];
        sc[s]=v; lmax=fmaxf(lmax,v);
    }
#pragma unroll
    for(int o=16;o>0;o>>=1) lmax=fmaxf(lmax,__shfl_xor_sync(0xffffffffu,lmax,o));
    if(lane==0) wred[warp]=lmax;
    __syncthreads();
    float m=wred[0];
#pragma unroll
    for(int w=1;w<8;w++) m=fmaxf(m,wred[w]);
    __syncthreads();
    float lsum=0.f;
    for(int s=tid;s<NS;s+=256){float e=expf(sc[s]-m);sc[s]=e;lsum+=e;}
#pragma unroll
    for(int o=16;o>0;o>>=1) lsum+=__shfl_xor_sync(0xffffffffu,lsum,o);
    if(lane==0) wred[warp]=lsum;
    __syncthreads();
    float tot=0.f;
#pragma unroll
    for(int w=0;w<8;w++) tot+=wred[w];
    const float inv=1.f/tot;
    for(int s=tid;s<NS;s+=256) attn[b*NS+s]=sc[s]*inv;
}

// ---- context[b,e] = sum_s attn[b,s]*enc[b,s,e] ----
__global__ void __launch_bounds__(128) context_kernel(const float* __restrict__ attn,
    const float* __restrict__ enc,float* __restrict__ x){
    __shared__ float aw[NS];
    const int b=blockIdx.x,e=blockIdx.y*128+threadIdx.x;
    for(int s=threadIdx.x;s<NS;s+=128) aw[s]=attn[b*NS+s];
    __syncthreads();
    float a0=0.f,a1=0.f,a2=0.f,a3=0.f;
    const float* ep=enc+(size_t)b*NS*1024+e;
    for(int s=0;s<NS;s+=4){
        a0+=aw[s+0]*ep[(size_t)(s+0)*1024];
        a1+=aw[s+1]*ep[(size_t)(s+1)*1024];
        a2+=aw[s+2]*ep[(size_t)(s+2)*1024];
        a3+=aw[s+3]*ep[(size_t)(s+3)*1024];
    }
    x[b*2048+1024+e]=(a0+a1)+(a2+a3);
}

// ---- LSTM pointwise ----
__global__ void __launch_bounds__(256) lstm_kernel(const float* __restrict__ gates,
    const float* __restrict__ cprev,float* __restrict__ hout,float* __restrict__ cout,
    float* __restrict__ hscratch){
    const int b=blockIdx.x;
    for(int j=threadIdx.x;j<1024;j+=256){
        float gi=gates[b*4096+j], gf=gates[b*4096+1024+j];
        float gg=gates[b*4096+2048+j], go=gates[b*4096+3072+j];
        float c=sigf(gf)*cprev[b*1024+j]+sigf(gi)*tanhf(gg);
        float h=sigf(go)*tanhf(c);
        hout[b*1024+j]=h; cout[b*1024+j]=c; hscratch[b*1024+j]=h;
    }
}

extern "C" void kernel_launch(void* const* d_in,const int* in_sizes,int n_in,
                              void* d_out,int out_size){
    const int*   step = (const int*)  d_in[0];
    const float* h0   = (const float*)d_in[1];
    const float* c0   = (const float*)d_in[2];
    const float* enc  = (const float*)d_in[3];
    const float* emb  = (const float*)d_in[4];
    const float* Wah  = (const float*)d_in[5];
    const float* bah  = (const float*)d_in[6];
    const float* Wae  = (const float*)d_in[7];
    const float* bae  = (const float*)d_in[8];
    const float* va   = (const float*)d_in[9];
    const float* Wih0 = (const float*)d_in[11];
    const float* Whh0 = (const float*)d_in[12];
    const float* bih0 = (const float*)d_in[13];
    const float* bhh0 = (const float*)d_in[14];
    const float* Wih1 = (const float*)d_in[15];
    const float* Whh1 = (const float*)d_in[16];
    const float* bih1 = (const float*)d_in[17];
    const float* bhh1 = (const float*)d_in[18];
    const float* Wout = (const float*)d_in[19];
    const float* bout = (const float*)d_in[20];
    float* out=(float*)d_out;

    float *q,*part,*x,*gates,*h1,*h2;
    cudaGetSymbolAddress((void**)&q,g_q);
    cudaGetSymbolAddress((void**)&part,g_part);
    cudaGetSymbolAddress((void**)&x,g_x);
    cudaGetSymbolAddress((void**)&gates,g_gates);
    cudaGetSymbolAddress((void**)&h1,g_h1);
    cudaGetSymbolAddress((void**)&h2,g_h2);

    embed_kernel<<<64,256>>>(step,emb,x);
    // q = h0[-1]@Wah^T + bah + bae
    gemm_tf32_kernel<false><<<8,128>>>(h0+64*1024,Wah,q,64,1024,1024,bah,bae);
    // fused attention scores (bf16 mma)
    score_kernel<<<dim3(8,512),128>>>(enc,Wae,q,va,part);
    softmax_kernel<<<64,256>>>(part,out+OUT_ATT);
    context_kernel<<<dim3(64,8),128>>>(out+OUT_ATT,enc,x);
    // layer 0
    gemm_tf32_kernel<false><<<32,128>>>(x,Wih0,gates,64,4096,2048,bih0,bhh0);
    gemm_tf32_kernel<true ><<<32,128>>>(h0,Whh0,gates,64,4096,1024,nullptr,nullptr);
    lstm_kernel<<<64,256>>>(gates,c0,out+OUT_H,out+OUT_C,h1);
    // layer 1
    gemm_tf32_kernel<false><<<32,128>>>(h1,Wih1,gates,64,4096,1024,bih1,bhh1);
    gemm_tf32_kernel<true ><<<32,128>>>(h0+64*1024,Whh1,gates,64,4096,1024,nullptr,nullptr);
    lstm_kernel<<<64,256>>>(gates,c0+64*1024,out+OUT_H+64*1024,out+OUT_C+64*1024,h2);
    // logits
    gemm_tf32_kernel<false><<<250,128>>>(h2,Wout,out,64,32000,1024,bout,nullptr);
}

// round 8
// speedup vs baseline: 2.6787x; 1.1677x over previous
#include <cuda_runtime.h>
#include <cuda_bf16.h>
#include <stdint.h>
#include <math.h>

#define NB 64
#define NS 1024
#define NV 32000
#define NH 1024
// out: logits[64*32000] | h_new[2*64*1024] | c_new[2*64*1024] | attn[64*1024]
#define OUT_H   (NB*NV)
#define OUT_C   (OUT_H + 2*NB*NH)
#define OUT_ATT (OUT_C + 2*NB*NH)

__device__ float g_q[NB*1024];
__device__ float g_part[4*NB*NS];
__device__ float g_x[NB*2048];
__device__ float g_gates[NB*4096];
__device__ float g_h1[NB*NH];
__device__ float g_h2[NB*NH];
__device__ __nv_bfloat16 g_encb[(size_t)NB*NS*1024];   // enc pre-converted to bf16
__device__ __nv_bfloat16 g_waeb[1024*1024];            // Wa_e pre-converted to bf16

__device__ __forceinline__ float fast_tanh(float x){float y;asm("tanh.approx.f32 %0,%1;":"=f"(y):"f"(x));return y;}
__device__ __forceinline__ float to_tf32(float x){uint32_t u;asm("cvt.rna.tf32.f32 %0,%1;":"=r"(u):"f"(x));return __uint_as_float(u);}
__device__ __forceinline__ float sigf(float x){return 1.f/(1.f+expf(-x));}

__device__ __forceinline__ uint32_t smem_u32(const void* p){
    uint32_t a; asm("{ .reg .u64 t; cvta.to.shared.u64 t, %1; cvt.u32.u64 %0, t; }":"=r"(a):"l"(p)); return a;
}
__device__ __forceinline__ void cp_async16(uint32_t dst,const void* src){
    asm volatile("cp.async.cg.shared.global [%0], [%1], 16;\n"::"r"(dst),"l"(src):"memory");
}
__device__ __forceinline__ void cp_commit(){
    asm volatile("cp.async.commit_group;\n":::"memory");
}

__device__ __forceinline__ void mma_tf32(float* c,const uint32_t* a,const uint32_t* b){
    asm volatile("mma.sync.aligned.m16n8k8.row.col.f32.tf32.tf32.f32 "
        "{%0,%1,%2,%3},{%4,%5,%6,%7},{%8,%9},{%0,%1,%2,%3};\n"
        : "+f"(c[0]),"+f"(c[1]),"+f"(c[2]),"+f"(c[3])
        : "r"(a[0]),"r"(a[1]),"r"(a[2]),"r"(a[3]),"r"(b[0]),"r"(b[1]));
}
__device__ __forceinline__ void mma_bf16(float* c,const uint32_t* a,const uint32_t* b){
    asm volatile("mma.sync.aligned.m16n8k16.row.col.f32.bf16.bf16.f32 "
        "{%0,%1,%2,%3},{%4,%5,%6,%7},{%8,%9},{%0,%1,%2,%3};\n"
        : "+f"(c[0]),"+f"(c[1]),"+f"(c[2]),"+f"(c[3])
        : "r"(a[0]),"r"(a[1]),"r"(a[2]),"r"(a[3]),"r"(b[0]),"r"(b[1]));
}
#define LDSM4(r0,r1,r2,r3,addr) \
    asm volatile("ldmatrix.sync.aligned.m8n8.x4.shared.b16 {%0,%1,%2,%3},[%4];" \
        : "=r"(r0),"=r"(r1),"=r"(r2),"=r"(r3) : "r"(addr))

// ---- fp32 -> bf16 conversion (grid-stride over float4) ----
__global__ void cvt_bf16_kernel(const float* __restrict__ in,__nv_bfloat16* __restrict__ out,int n4){
    int i=blockIdx.x*blockDim.x+threadIdx.x;
    const float4* in4=reinterpret_cast<const float4*>(in);
    uint2* out2=reinterpret_cast<uint2*>(out);
    for(;i<n4;i+=gridDim.x*blockDim.x){
        float4 v=in4[i];
        __nv_bfloat162 lo=__floats2bfloat162_rn(v.x,v.y);
        __nv_bfloat162 hi=__floats2bfloat162_rn(v.z,v.w);
        uint2 u; u.x=*reinterpret_cast<uint32_t*>(&lo); u.y=*reinterpret_cast<uint32_t*>(&hi);
        out2[i]=u;
    }
}

// ---- embed: g_x[b][0:1024] = emb[step[b]] ----
__global__ void embed_kernel(const int* __restrict__ step,const float* __restrict__ emb,float* __restrict__ x){
    int b=blockIdx.x; int idx=step[b];
    for(int j=threadIdx.x;j<1024;j+=256) x[b*2048+j]=emb[(size_t)idx*1024+j];
}

// ===========================================================================
// Fused attention-score GEMM v3 (bf16 mma + cp.async 4-stage):
//   part[nt][m] = sum_{n in 256-tile nt} va[n]*tanh(q[b(m),n] + enc[m,:]@Wae[n,:])
// CTA tile 128(M)x256(N), 8 warps (2Mx4N), warp 64x64, K per stage 32, 4 stages.
// Smem rows 64B; swizzle seg ^= (row>>1)&3 (conflict-free cp.async + ldmatrix).
// ===========================================================================
#define SC_STAGE_BYTES 24576              // A 128*64 + B 256*64
#define SC_SMEM (4*SC_STAGE_BYTES)        // 98304

__global__ void __launch_bounds__(256,1) score_kernel(
    const __nv_bfloat16* __restrict__ encb,const __nv_bfloat16* __restrict__ waeb,
    const float* __restrict__ q,const float* __restrict__ va,float* __restrict__ part)
{
    extern __shared__ __align__(128) char dyn[];
    __shared__ float red[128][4];
    __shared__ float2 qa[256];

    const uint32_t base=smem_u32(dyn);
    const int tid=threadIdx.x,lane=tid&31,warp=tid>>5;
    const int wm=warp&1,wn=warp>>1;          // 2 (M) x 4 (N)
    const int g=lane>>2,t=lane&3;
    const int m0=blockIdx.y*128, n0=blockIdx.x*256;
    const int b=blockIdx.y>>3;               // 8 m-tiles per batch row

    qa[tid]=make_float2(q[b*1024+n0+tid], va[n0+tid]);

    // per-lane ldmatrix address components
    const int rA=wm*64+(lane&15);            // A row
    const int hiA=lane>>4;                   // k-seg half
    const uint32_t sxA=((uint32_t)rA>>1)&3;
    const int rB=wn*64+(lane&7)+((lane>>4)<<3);
    const int hiB=(lane>>3)&1;
    const uint32_t sxB=((uint32_t)rB>>1)&3;
    uint32_t aoff[2],boff[2];
#pragma unroll
    for(int kk=0;kk<2;kk++){
        aoff[kk]=(uint32_t)rA*64+((((uint32_t)(2*kk+hiA))^sxA)<<4);
        boff[kk]=8192u+(uint32_t)rB*64+((((uint32_t)(2*kk+hiB))^sxB)<<4);
    }

    float acc[4][8][4];
#pragma unroll
    for(int i=0;i<4;i++)
#pragma unroll
      for(int j=0;j<8;j++)
#pragma unroll
        for(int k=0;k<4;k++) acc[i][j][k]=0.f;

    auto fill=[&](int s,int k0){
        const uint32_t sbase=base+(uint32_t)s*SC_STAGE_BYTES;
#pragma unroll
        for(int j=0;j<2;j++){                // A: 128 rows x 4 segs
            int idx=tid+256*j; int r=idx>>2, seg=idx&3;
            uint32_t dst=sbase+(uint32_t)r*64+((((uint32_t)seg)^(((uint32_t)r>>1)&3))<<4);
            cp_async16(dst, encb+(size_t)(m0+r)*1024+k0+seg*8);
        }
#pragma unroll
        for(int j=0;j<4;j++){                // B: 256 rows x 4 segs
            int idx=tid+256*j; int r=idx>>2, seg=idx&3;
            uint32_t dst=sbase+8192u+(uint32_t)r*64+((((uint32_t)seg)^(((uint32_t)r>>1)&3))<<4);
            cp_async16(dst, waeb+(size_t)(n0+r)*1024+k0+seg*8);
        }
        cp_commit();
    };

    fill(0,0); fill(1,32); fill(2,64);
#pragma unroll 1
    for(int i=0;i<32;i++){
        asm volatile("cp.async.wait_group 2;\n":::"memory");
        __syncthreads();
        const uint32_t sb2=base+(uint32_t)(i&3)*SC_STAGE_BYTES;
#pragma unroll
        for(int kk=0;kk<2;kk++){
            uint32_t af[4][4];
#pragma unroll
            for(int mi=0;mi<4;mi++)
                LDSM4(af[mi][0],af[mi][1],af[mi][2],af[mi][3], sb2+aoff[kk]+(uint32_t)mi*1024);
            uint32_t bf[8][2];
#pragma unroll
            for(int p=0;p<4;p++)
                LDSM4(bf[2*p][0],bf[2*p][1],bf[2*p+1][0],bf[2*p+1][1], sb2+boff[kk]+(uint32_t)p*1024);
#pragma unroll
            for(int mi=0;mi<4;mi++)
#pragma unroll
                for(int ni=0;ni<8;ni++) mma_bf16(acc[mi][ni],af[mi],bf[ni]);
        }
        if(i+3<32) fill((i+3)&3,(i+3)*32);
        else cp_commit();
    }

    // epilogue: va*tanh(q + k), reduce over this CTA's 256 n-columns
    float rs[4][2];
#pragma unroll
    for(int mi=0;mi<4;mi++){rs[mi][0]=0.f;rs[mi][1]=0.f;}
#pragma unroll
    for(int ni=0;ni<8;ni++){
        int col=wn*64+ni*8+2*t;
        float2 qa0=qa[col], qa1=qa[col+1];
#pragma unroll
        for(int mi=0;mi<4;mi++){
            rs[mi][0]+=qa0.y*fast_tanh(qa0.x+acc[mi][ni][0])+qa1.y*fast_tanh(qa1.x+acc[mi][ni][1]);
            rs[mi][1]+=qa0.y*fast_tanh(qa0.x+acc[mi][ni][2])+qa1.y*fast_tanh(qa1.x+acc[mi][ni][3]);
        }
    }
#pragma unroll
    for(int o=1;o<4;o<<=1)
#pragma unroll
      for(int mi=0;mi<4;mi++){
        rs[mi][0]+=__shfl_xor_sync(0xffffffffu,rs[mi][0],o);
        rs[mi][1]+=__shfl_xor_sync(0xffffffffu,rs[mi][1],o);
      }
    if(t==0)
#pragma unroll
      for(int mi=0;mi<4;mi++){
        red[wm*64+mi*16+g][wn]=rs[mi][0];
        red[wm*64+mi*16+8+g][wn]=rs[mi][1];
      }
    __syncthreads();
    if(tid<128)
        part[(size_t)blockIdx.x*(NB*NS)+m0+tid]=(red[tid][0]+red[tid][1])+(red[tid][2]+red[tid][3]);
}

// ---- generic skinny GEMM: C[M<=64,N] = A[M,K]@B[N,K]^T (+bias or +=), tf32 ----
template<bool ACC>
__global__ void __launch_bounds__(128) gemm_tf32_kernel(
    const float* __restrict__ A,const float* __restrict__ Bm,float* __restrict__ C,
    int M,int N,int K,const float* __restrict__ bias1,const float* __restrict__ bias2)
{
    __shared__ float As[2][64][20];
    __shared__ float Bs[2][128][20];
    const int tid=threadIdx.x,lane=tid&31,warp=tid>>5;
    const int wm=warp&1,wn=warp>>1,g=lane>>2,t=lane&3;
    const int n0=blockIdx.x*128;
    float acc[2][8][4];
#pragma unroll
    for(int i=0;i<2;i++)
#pragma unroll
      for(int j=0;j<8;j++)
#pragma unroll
        for(int k=0;k<4;k++) acc[i][j][k]=0.f;
    float4 ra[2],rb[4];
    auto ldg=[&](int k0){
#pragma unroll
        for(int j=0;j<2;j++){int i=tid+128*j,r=i>>2,cb=i&3;
            ra[j]=*reinterpret_cast<const float4*>(A+(size_t)r*K+k0+cb*4);}
#pragma unroll
        for(int j=0;j<4;j++){int i=tid+128*j,r=i>>2,cb=i&3;
            rb[j]=*reinterpret_cast<const float4*>(Bm+(size_t)(n0+r)*K+k0+cb*4);}
    };
    auto sts=[&](int buf){
#pragma unroll
        for(int j=0;j<2;j++){int i=tid+128*j,r=i>>2,cb=i&3;
            As[buf][r][cb*4+0]=to_tf32(ra[j].x);As[buf][r][cb*4+1]=to_tf32(ra[j].y);
            As[buf][r][cb*4+2]=to_tf32(ra[j].z);As[buf][r][cb*4+3]=to_tf32(ra[j].w);}
#pragma unroll
        for(int j=0;j<4;j++){int i=tid+128*j,r=i>>2,cb=i&3;
            Bs[buf][r][cb*4+0]=to_tf32(rb[j].x);Bs[buf][r][cb*4+1]=to_tf32(rb[j].y);
            Bs[buf][r][cb*4+2]=to_tf32(rb[j].z);Bs[buf][r][cb*4+3]=to_tf32(rb[j].w);}
    };
    ldg(0);sts(0);__syncthreads();
    const int nst=K/16;
    for(int s=0;s<nst;s++){
        const int cur=s&1;
        if(s+1<nst) ldg((s+1)*16);
#pragma unroll
        for(int kk=0;kk<2;kk++){
            const int kb=kk*8;
            uint32_t af[2][4];
#pragma unroll
            for(int mi=0;mi<2;mi++){int mr=wm*32+mi*16;
                af[mi][0]=__float_as_uint(As[cur][mr+g][kb+t]);
                af[mi][1]=__float_as_uint(As[cur][mr+g+8][kb+t]);
                af[mi][2]=__float_as_uint(As[cur][mr+g][kb+t+4]);
                af[mi][3]=__float_as_uint(As[cur][mr+g+8][kb+t+4]);}
            uint32_t bf[8][2];
#pragma unroll
            for(int ni=0;ni<8;ni++){int nr=wn*64+ni*8+g;
                bf[ni][0]=__float_as_uint(Bs[cur][nr][kb+t]);
                bf[ni][1]=__float_as_uint(Bs[cur][nr][kb+t+4]);}
#pragma unroll
            for(int mi=0;mi<2;mi++)
#pragma unroll
                for(int ni=0;ni<8;ni++) mma_tf32(acc[mi][ni],af[mi],bf[ni]);
        }
        if(s+1<nst) sts(cur^1);
        __syncthreads();
    }
#pragma unroll
    for(int mi=0;mi<2;mi++)
#pragma unroll
      for(int ni=0;ni<8;ni++){
        int row=wm*32+mi*16+g, col=n0+wn*64+ni*8+2*t;
        float b0=0.f,b1=0.f;
        if(!ACC){ if(bias1){b0+=bias1[col];b1+=bias1[col+1];}
                  if(bias2){b0+=bias2[col];b1+=bias2[col+1];} }
        if(row<M){float* p=C+(size_t)row*N+col;
            if(ACC){p[0]+=acc[mi][ni][0];p[1]+=acc[mi][ni][1];}
            else   {p[0]=acc[mi][ni][0]+b0;p[1]=acc[mi][ni][1]+b1;}}
        if(row+8<M){float* p=C+(size_t)(row+8)*N+col;
            if(ACC){p[0]+=acc[mi][ni][2];p[1]+=acc[mi][ni][3];}
            else   {p[0]=acc[mi][ni][2]+b0;p[1]=acc[mi][ni][3]+b1;}}
      }
}

// ---- softmax over S per batch row (4 partial slabs) ----
__global__ void __launch_bounds__(256) softmax_kernel(const float* __restrict__ part,float* __restrict__ attn){
    __shared__ float sc[NS];
    __shared__ float wred[8];
    const int b=blockIdx.x,tid=threadIdx.x,lane=tid&31,warp=tid>>5;
    float lmax=-1e30f;
    for(int s=tid;s<NS;s+=256){
        float v=0.f;
#pragma unroll
        for(int p=0;p<4;p++) v+=part[(size_t)p*(NB*NS)+b*NS+s];
        sc[s]=v; lmax=fmaxf(lmax,v);
    }
#pragma unroll
    for(int o=16;o>0;o>>=1) lmax=fmaxf(lmax,__shfl_xor_sync(0xffffffffu,lmax,o));
    if(lane==0) wred[warp]=lmax;
    __syncthreads();
    float m=wred[0];
#pragma unroll
    for(int w=1;w<8;w++) m=fmaxf(m,wred[w]);
    __syncthreads();
    float lsum=0.f;
    for(int s=tid;s<NS;s+=256){float e=expf(sc[s]-m);sc[s]=e;lsum+=e;}
#pragma unroll
    for(int o=16;o>0;o>>=1) lsum+=__shfl_xor_sync(0xffffffffu,lsum,o);
    if(lane==0) wred[warp]=lsum;
    __syncthreads();
    float tot=0.f;
#pragma unroll
    for(int w=0;w<8;w++) tot+=wred[w];
    const float inv=1.f/tot;
    for(int s=tid;s<NS;s+=256) attn[b*NS+s]=sc[s]*inv;
}

// ---- context[b,e] = sum_s attn[b,s]*enc[b,s,e] ----
__global__ void __launch_bounds__(128) context_kernel(const float* __restrict__ attn,
    const float* __restrict__ enc,float* __restrict__ x){
    __shared__ float aw[NS];
    const int b=blockIdx.x,e=blockIdx.y*128+threadIdx.x;
    for(int s=threadIdx.x;s<NS;s+=128) aw[s]=attn[b*NS+s];
    __syncthreads();
    float a0=0.f,a1=0.f,a2=0.f,a3=0.f;
    const float* ep=enc+(size_t)b*NS*1024+e;
    for(int s=0;s<NS;s+=4){
        a0+=aw[s+0]*ep[(size_t)(s+0)*1024];
        a1+=aw[s+1]*ep[(size_t)(s+1)*1024];
        a2+=aw[s+2]*ep[(size_t)(s+2)*1024];
        a3+=aw[s+3]*ep[(size_t)(s+3)*1024];
    }
    x[b*2048+1024+e]=(a0+a1)+(a2+a3);
}

// ---- LSTM pointwise ----
__global__ void __launch_bounds__(256) lstm_kernel(const float* __restrict__ gates,
    const float* __restrict__ cprev,float* __restrict__ hout,float* __restrict__ cout,
    float* __restrict__ hscratch){
    const int b=blockIdx.x;
    for(int j=threadIdx.x;j<1024;j+=256){
        float gi=gates[b*4096+j], gf=gates[b*4096+1024+j];
        float gg=gates[b*4096+2048+j], go=gates[b*4096+3072+j];
        float c=sigf(gf)*cprev[b*1024+j]+sigf(gi)*tanhf(gg);
        float h=sigf(go)*tanhf(c);
        hout[b*1024+j]=h; cout[b*1024+j]=c; hscratch[b*1024+j]=h;
    }
}

extern "C" void kernel_launch(void* const* d_in,const int* in_sizes,int n_in,
                              void* d_out,int out_size){
    const int*   step = (const int*)  d_in[0];
    const float* h0   = (const float*)d_in[1];
    const float* c0   = (const float*)d_in[2];
    const float* enc  = (const float*)d_in[3];
    const float* emb  = (const float*)d_in[4];
    const float* Wah  = (const float*)d_in[5];
    const float* bah  = (const float*)d_in[6];
    const float* Wae  = (const float*)d_in[7];
    const float* bae  = (const float*)d_in[8];
    const float* va   = (const float*)d_in[9];
    const float* Wih0 = (const float*)d_in[11];
    const float* Whh0 = (const float*)d_in[12];
    const float* bih0 = (const float*)d_in[13];
    const float* bhh0 = (const float*)d_in[14];
    const float* Wih1 = (const float*)d_in[15];
    const float* Whh1 = (const float*)d_in[16];
    const float* bih1 = (const float*)d_in[17];
    const float* bhh1 = (const float*)d_in[18];
    const float* Wout = (const float*)d_in[19];
    const float* bout = (const float*)d_in[20];
    float* out=(float*)d_out;

    float *q,*part,*x,*gates,*h1,*h2;
    __nv_bfloat16 *encb,*waeb;
    cudaGetSymbolAddress((void**)&q,g_q);
    cudaGetSymbolAddress((void**)&part,g_part);
    cudaGetSymbolAddress((void**)&x,g_x);
    cudaGetSymbolAddress((void**)&gates,g_gates);
    cudaGetSymbolAddress((void**)&h1,g_h1);
    cudaGetSymbolAddress((void**)&h2,g_h2);
    cudaGetSymbolAddress((void**)&encb,g_encb);
    cudaGetSymbolAddress((void**)&waeb,g_waeb);

    cudaFuncSetAttribute(score_kernel,cudaFuncAttributeMaxDynamicSharedMemorySize,SC_SMEM);

    // pre-convert enc + Wae to bf16
    cvt_bf16_kernel<<<8192,256>>>(enc,encb,(NB*NS*1024)/4);
    cvt_bf16_kernel<<<1024,256>>>(Wae,waeb,(1024*1024)/4);
    embed_kernel<<<64,256>>>(step,emb,x);
    // q = h0[-1]@Wah^T + bah + bae
    gemm_tf32_kernel<false><<<8,128>>>(h0+64*1024,Wah,q,64,1024,1024,bah,bae);
    // fused attention scores (bf16 mma, cp.async 4-stage)
    score_kernel<<<dim3(4,512),256,SC_SMEM>>>(encb,waeb,q,va,part);
    softmax_kernel<<<64,256>>>(part,out+OUT_ATT);
    context_kernel<<<dim3(64,8),128>>>(out+OUT_ATT,enc,x);
    // layer 0
    gemm_tf32_kernel<false><<<32,128>>>(x,Wih0,gates,64,4096,2048,bih0,bhh0);
    gemm_tf32_kernel<true ><<<32,128>>>(h0,Whh0,gates,64,4096,1024,nullptr,nullptr);
    lstm_kernel<<<64,256>>>(gates,c0,out+OUT_H,out+OUT_C,h1);
    // layer 1
    gemm_tf32_kernel<false><<<32,128>>>(h1,Wih1,gates,64,4096,1024,bih1,bhh1);
    gemm_tf32_kernel<true ><<<32,128>>>(h0+64*1024,Whh1,gates,64,4096,1024,nullptr,nullptr);
    lstm_kernel<<<64,256>>>(gates,c0+64*1024,out+OUT_H+64*1024,out+OUT_C+64*1024,h2);
    // logits
    gemm_tf32_kernel<false><<<250,128>>>(h2,Wout,out,64,32000,1024,bout,nullptr);
}

// round 10
// speedup vs baseline: 3.4960x; 1.3051x over previous
#include <cuda_runtime.h>
#include <cuda_bf16.h>
#include <stdint.h>
#include <math.h>

#define NB 64
#define NS 1024
#define NV 32000
#define NH 1024
// out: logits[64*32000] | h_new[2*64*1024] | c_new[2*64*1024] | attn[64*1024]
#define OUT_H   (NB*NV)
#define OUT_C   (OUT_H + 2*NB*NH)
#define OUT_ATT (OUT_C + 2*NB*NH)
#define SK 8            // K-splits for skinny GEMMs

__device__ float g_q[NB*1024];
__device__ float g_part[4*NB*NS];
__device__ float g_xh0[NB*3072];      // [emb | context | h0[0]]
__device__ float g_xh1[NB*2048];      // [h1 | h0[1]]
__device__ float g_h2[NB*NH];
__device__ float g_sk[SK*NB*4096];    // split-K partials (8 MB)
__device__ __nv_bfloat16 g_encb[(size_t)NB*NS*1024];
__device__ __nv_bfloat16 g_waeb[1024*1024];

__device__ __forceinline__ float fast_tanh(float x){float y;asm("tanh.approx.f32 %0,%1;":"=f"(y):"f"(x));return y;}
__device__ __forceinline__ float to_tf32(float x){uint32_t u;asm("cvt.rna.tf32.f32 %0,%1;":"=r"(u):"f"(x));return __uint_as_float(u);}
__device__ __forceinline__ float sigf(float x){return 1.f/(1.f+expf(-x));}

__device__ __forceinline__ uint32_t smem_u32(const void* p){
    uint32_t a; asm("{ .reg .u64 t; cvta.to.shared.u64 t, %1; cvt.u32.u64 %0, t; }":"=r"(a):"l"(p)); return a;
}
__device__ __forceinline__ void cp_async16(uint32_t dst,const void* src){
    asm volatile("cp.async.cg.shared.global [%0], [%1], 16;\n"::"r"(dst),"l"(src):"memory");
}
__device__ __forceinline__ void cp_commit(){
    asm volatile("cp.async.commit_group;\n":::"memory");
}

__device__ __forceinline__ void mma_tf32(float* c,const uint32_t* a,const uint32_t* b){
    asm volatile("mma.sync.aligned.m16n8k8.row.col.f32.tf32.tf32.f32 "
        "{%0,%1,%2,%3},{%4,%5,%6,%7},{%8,%9},{%0,%1,%2,%3};\n"
        : "+f"(c[0]),"+f"(c[1]),"+f"(c[2]),"+f"(c[3])
        : "r"(a[0]),"r"(a[1]),"r"(a[2]),"r"(a[3]),"r"(b[0]),"r"(b[1]));
}
__device__ __forceinline__ void mma_bf16(float* c,const uint32_t* a,const uint32_t* b){
    asm volatile("mma.sync.aligned.m16n8k16.row.col.f32.bf16.bf16.f32 "
        "{%0,%1,%2,%3},{%4,%5,%6,%7},{%8,%9},{%0,%1,%2,%3};\n"
        : "+f"(c[0]),"+f"(c[1]),"+f"(c[2]),"+f"(c[3])
        : "r"(a[0]),"r"(a[1]),"r"(a[2]),"r"(a[3]),"r"(b[0]),"r"(b[1]));
}
#define LDSM4(r0,r1,r2,r3,addr) \
    asm volatile("ldmatrix.sync.aligned.m8n8.x4.shared.b16 {%0,%1,%2,%3},[%4];" \
        : "=r"(r0),"=r"(r1),"=r"(r2),"=r"(r3) : "r"(addr))

// ---- fp32 -> bf16 conversion ----
__global__ void cvt_bf16_kernel(const float* __restrict__ in,__nv_bfloat16* __restrict__ out,int n4){
    int i=blockIdx.x*blockDim.x+threadIdx.x;
    const float4* in4=reinterpret_cast<const float4*>(in);
    uint2* out2=reinterpret_cast<uint2*>(out);
    for(;i<n4;i+=gridDim.x*blockDim.x){
        float4 v=in4[i];
        __nv_bfloat162 lo=__floats2bfloat162_rn(v.x,v.y);
        __nv_bfloat162 hi=__floats2bfloat162_rn(v.z,v.w);
        uint2 u; u.x=*reinterpret_cast<uint32_t*>(&lo); u.y=*reinterpret_cast<uint32_t*>(&hi);
        out2[i]=u;
    }
}

// ---- embed + stage h0 rows into concat buffers ----
__global__ void stage_kernel(const int* __restrict__ step,const float* __restrict__ emb,
    const float* __restrict__ h0,float* __restrict__ xh0,float* __restrict__ xh1){
    int b=blockIdx.x; int idx=step[b];
    for(int j=threadIdx.x;j<1024;j+=256){
        xh0[b*3072+j]=emb[(size_t)idx*1024+j];
        xh0[b*3072+2048+j]=h0[b*1024+j];          // h0 layer0
        xh1[b*2048+1024+j]=h0[65536+b*1024+j];    // h0 layer1
    }
}

// ===========================================================================
// Split-K skinny GEMM: part[z][64][N] = A[64, zKc:(z+1)Kc] @ Bcat[N, ...]^T
// Bcat = [B1 (K1 cols) | B2 (K-K1 cols)] selected per load. tf32 path.
// ===========================================================================
__global__ void __launch_bounds__(128) gemm_sk(
    const float* __restrict__ A,const float* __restrict__ B1,const float* __restrict__ B2,
    float* __restrict__ part,int N,int K1,int K,int Kc)
{
    __shared__ float As[2][64][20];
    __shared__ float Bs[2][128][20];
    const int tid=threadIdx.x,lane=tid&31,warp=tid>>5;
    const int wm=warp&1,wn=warp>>1,g=lane>>2,t=lane&3;
    const int n0=blockIdx.x*128;
    const int z=blockIdx.y, kbase=z*Kc, K2=K-K1;
    float acc[2][8][4];
#pragma unroll
    for(int i=0;i<2;i++)
#pragma unroll
      for(int j=0;j<8;j++)
#pragma unroll
        for(int k=0;k<4;k++) acc[i][j][k]=0.f;
    float4 ra[2],rb[4];
    auto ldg=[&](int k0){
        int kg=kbase+k0;
#pragma unroll
        for(int j=0;j<2;j++){int i=tid+128*j,r=i>>2,cb=i&3;
            ra[j]=*reinterpret_cast<const float4*>(A+(size_t)r*K+kg+cb*4);}
#pragma unroll
        for(int j=0;j<4;j++){int i=tid+128*j,r=i>>2,cb=i&3;
            int kk=kg+cb*4;
            const float* src=(kk<K1)? B1+(size_t)(n0+r)*K1+kk : B2+(size_t)(n0+r)*K2+(kk-K1);
            rb[j]=*reinterpret_cast<const float4*>(src);}
    };
    auto sts=[&](int buf){
#pragma unroll
        for(int j=0;j<2;j++){int i=tid+128*j,r=i>>2,cb=i&3;
            As[buf][r][cb*4+0]=to_tf32(ra[j].x);As[buf][r][cb*4+1]=to_tf32(ra[j].y);
            As[buf][r][cb*4+2]=to_tf32(ra[j].z);As[buf][r][cb*4+3]=to_tf32(ra[j].w);}
#pragma unroll
        for(int j=0;j<4;j++){int i=tid+128*j,r=i>>2,cb=i&3;
            Bs[buf][r][cb*4+0]=to_tf32(rb[j].x);Bs[buf][r][cb*4+1]=to_tf32(rb[j].y);
            Bs[buf][r][cb*4+2]=to_tf32(rb[j].z);Bs[buf][r][cb*4+3]=to_tf32(rb[j].w);}
    };
    ldg(0);sts(0);__syncthreads();
    const int nst=Kc/16;
    for(int s=0;s<nst;s++){
        const int cur=s&1;
        if(s+1<nst) ldg((s+1)*16);
#pragma unroll
        for(int kk=0;kk<2;kk++){
            const int kb=kk*8;
            uint32_t af[2][4];
#pragma unroll
            for(int mi=0;mi<2;mi++){int mr=wm*32+mi*16;
                af[mi][0]=__float_as_uint(As[cur][mr+g][kb+t]);
                af[mi][1]=__float_as_uint(As[cur][mr+g+8][kb+t]);
                af[mi][2]=__float_as_uint(As[cur][mr+g][kb+t+4]);
                af[mi][3]=__float_as_uint(As[cur][mr+g+8][kb+t+4]);}
            uint32_t bf[8][2];
#pragma unroll
            for(int ni=0;ni<8;ni++){int nr=wn*64+ni*8+g;
                bf[ni][0]=__float_as_uint(Bs[cur][nr][kb+t]);
                bf[ni][1]=__float_as_uint(Bs[cur][nr][kb+t+4]);}
#pragma unroll
            for(int mi=0;mi<2;mi++)
#pragma unroll
                for(int ni=0;ni<8;ni++) mma_tf32(acc[mi][ni],af[mi],bf[ni]);
        }
        if(s+1<nst) sts(cur^1);
        __syncthreads();
    }
    float* out=part+(size_t)z*64*N;
#pragma unroll
    for(int mi=0;mi<2;mi++)
#pragma unroll
      for(int ni=0;ni<8;ni++){
        int row=wm*32+mi*16+g, col=n0+wn*64+ni*8+2*t;
        float* p=out+(size_t)row*N+col;
        p[0]=acc[mi][ni][0]; p[1]=acc[mi][ni][1];
        p=out+(size_t)(row+8)*N+col;
        p[0]=acc[mi][ni][2]; p[1]=acc[mi][ni][3];
      }
}

// ---- q = sum_z part + bah + bae ----
__global__ void reduce_q_kernel(const float* __restrict__ part,const float* __restrict__ b1,
    const float* __restrict__ b2,float* __restrict__ q){
    int i=blockIdx.x*256+threadIdx.x;   // over 64*1024
    int n=i&1023;
    float v=b1[n]+b2[n];
#pragma unroll
    for(int z=0;z<SK;z++) v+=part[(size_t)z*65536+i];
    q[i]=v;
}

// ---- LSTM from split-K partials: gates = sum_z part + bi + bh -> h,c ----
// hstride: row stride of the h scratch buffer (2048 for xh1, 1024 for h2)
__global__ void __launch_bounds__(256) lstm_red_kernel(const float* __restrict__ part,
    const float* __restrict__ bi,const float* __restrict__ bh,
    const float* __restrict__ cprev,float* __restrict__ hout,float* __restrict__ cout,
    float* __restrict__ hscr,int hstride){
    const int b=blockIdx.x;
    for(int j=threadIdx.x;j<1024;j+=256){
        float gsum[4];
#pragma unroll
        for(int gi2=0;gi2<4;gi2++){
            int col=gi2*1024+j;
            float v=bi[col]+bh[col];
#pragma unroll
            for(int z=0;z<SK;z++) v+=part[(size_t)z*262144+b*4096+col];
            gsum[gi2]=v;
        }
        float c=sigf(gsum[1])*cprev[b*1024+j]+sigf(gsum[0])*tanhf(gsum[2]);
        float h=sigf(gsum[3])*tanhf(c);
        hout[b*1024+j]=h; cout[b*1024+j]=c; hscr[(size_t)b*hstride+j]=h;
    }
}

// ===========================================================================
// Fused attention-score GEMM (bf16 mma + cp.async 4-stage)
// ===========================================================================
#define SC_STAGE_BYTES 24576
#define SC_SMEM (4*SC_STAGE_BYTES)

__global__ void __launch_bounds__(256,1) score_kernel(
    const __nv_bfloat16* __restrict__ encb,const __nv_bfloat16* __restrict__ waeb,
    const float* __restrict__ q,const float* __restrict__ va,float* __restrict__ part)
{
    extern __shared__ __align__(128) char dyn[];
    __shared__ float red[128][4];
    __shared__ float2 qa[256];

    const uint32_t base=smem_u32(dyn);
    const int tid=threadIdx.x,lane=tid&31,warp=tid>>5;
    const int wm=warp&1,wn=warp>>1;
    const int g=lane>>2,t=lane&3;
    const int m0=blockIdx.y*128, n0=blockIdx.x*256;
    const int b=blockIdx.y>>3;

    qa[tid]=make_float2(q[b*1024+n0+tid], va[n0+tid]);

    const int rA=wm*64+(lane&15);
    const int hiA=lane>>4;
    const uint32_t sxA=((uint32_t)rA>>1)&3;
    const int rB=wn*64+(lane&7)+((lane>>4)<<3);
    const int hiB=(lane>>3)&1;
    const uint32_t sxB=((uint32_t)rB>>1)&3;
    uint32_t aoff[2],boff[2];
#pragma unroll
    for(int kk=0;kk<2;kk++){
        aoff[kk]=(uint32_t)rA*64+((((uint32_t)(2*kk+hiA))^sxA)<<4);
        boff[kk]=8192u+(uint32_t)rB*64+((((uint32_t)(2*kk+hiB))^sxB)<<4);
    }

    float acc[4][8][4];
#pragma unroll
    for(int i=0;i<4;i++)
#pragma unroll
      for(int j=0;j<8;j++)
#pragma unroll
        for(int k=0;k<4;k++) acc[i][j][k]=0.f;

    auto fill=[&](int s,int k0){
        const uint32_t sbase=base+(uint32_t)s*SC_STAGE_BYTES;
#pragma unroll
        for(int j=0;j<2;j++){
            int idx=tid+256*j; int r=idx>>2, seg=idx&3;
            uint32_t dst=sbase+(uint32_t)r*64+((((uint32_t)seg)^(((uint32_t)r>>1)&3))<<4);
            cp_async16(dst, encb+(size_t)(m0+r)*1024+k0+seg*8);
        }
#pragma unroll
        for(int j=0;j<4;j++){
            int idx=tid+256*j; int r=idx>>2, seg=idx&3;
            uint32_t dst=sbase+8192u+(uint32_t)r*64+((((uint32_t)seg)^(((uint32_t)r>>1)&3))<<4);
            cp_async16(dst, waeb+(size_t)(n0+r)*1024+k0+seg*8);
        }
        cp_commit();
    };

    fill(0,0); fill(1,32); fill(2,64);
#pragma unroll 1
    for(int i=0;i<32;i++){
        asm volatile("cp.async.wait_group 2;\n":::"memory");
        __syncthreads();
        const uint32_t sb2=base+(uint32_t)(i&3)*SC_STAGE_BYTES;
#pragma unroll
        for(int kk=0;kk<2;kk++){
            uint32_t af[4][4];
#pragma unroll
            for(int mi=0;mi<4;mi++)
                LDSM4(af[mi][0],af[mi][1],af[mi][2],af[mi][3], sb2+aoff[kk]+(uint32_t)mi*1024);
            uint32_t bf[8][2];
#pragma unroll
            for(int p=0;p<4;p++)
                LDSM4(bf[2*p][0],bf[2*p][1],bf[2*p+1][0],bf[2*p+1][1], sb2+boff[kk]+(uint32_t)p*1024);
#pragma unroll
            for(int mi=0;mi<4;mi++)
#pragma unroll
                for(int ni=0;ni<8;ni++) mma_bf16(acc[mi][ni],af[mi],bf[ni]);
        }
        if(i+3<32) fill((i+3)&3,(i+3)*32);
        else cp_commit();
    }

    float rs[4][2];
#pragma unroll
    for(int mi=0;mi<4;mi++){rs[mi][0]=0.f;rs[mi][1]=0.f;}
#pragma unroll
    for(int ni=0;ni<8;ni++){
        int col=wn*64+ni*8+2*t;
        float2 qa0=qa[col], qa1=qa[col+1];
#pragma unroll
        for(int mi=0;mi<4;mi++){
            rs[mi][0]+=qa0.y*fast_tanh(qa0.x+acc[mi][ni][0])+qa1.y*fast_tanh(qa1.x+acc[mi][ni][1]);
            rs[mi][1]+=qa0.y*fast_tanh(qa0.x+acc[mi][ni][2])+qa1.y*fast_tanh(qa1.x+acc[mi][ni][3]);
        }
    }
#pragma unroll
    for(int o=1;o<4;o<<=1)
#pragma unroll
      for(int mi=0;mi<4;mi++){
        rs[mi][0]+=__shfl_xor_sync(0xffffffffu,rs[mi][0],o);
        rs[mi][1]+=__shfl_xor_sync(0xffffffffu,rs[mi][1],o);
      }
    if(t==0)
#pragma unroll
      for(int mi=0;mi<4;mi++){
        red[wm*64+mi*16+g][wn]=rs[mi][0];
        red[wm*64+mi*16+8+g][wn]=rs[mi][1];
      }
    __syncthreads();
    if(tid<128)
        part[(size_t)blockIdx.x*(NB*NS)+m0+tid]=(red[tid][0]+red[tid][1])+(red[tid][2]+red[tid][3]);
}

// ---- full-size non-split GEMM (logits): C[64,N] = A@B^T + bias ----
__global__ void __launch_bounds__(128) gemm_tf32_kernel(
    const float* __restrict__ A,const float* __restrict__ Bm,float* __restrict__ C,
    int M,int N,int K,const float* __restrict__ bias1)
{
    __shared__ float As[2][64][20];
    __shared__ float Bs[2][128][20];
    const int tid=threadIdx.x,lane=tid&31,warp=tid>>5;
    const int wm=warp&1,wn=warp>>1,g=lane>>2,t=lane&3;
    const int n0=blockIdx.x*128;
    float acc[2][8][4];
#pragma unroll
    for(int i=0;i<2;i++)
#pragma unroll
      for(int j=0;j<8;j++)
#pragma unroll
        for(int k=0;k<4;k++) acc[i][j][k]=0.f;
    float4 ra[2],rb[4];
    auto ldg=[&](int k0){
#pragma unroll
        for(int j=0;j<2;j++){int i=tid+128*j,r=i>>2,cb=i&3;
            ra[j]=*reinterpret_cast<const float4*>(A+(size_t)r*K+k0+cb*4);}
#pragma unroll
        for(int j=0;j<4;j++){int i=tid+128*j,r=i>>2,cb=i&3;
            rb[j]=*reinterpret_cast<const float4*>(Bm+(size_t)(n0+r)*K+k0+cb*4);}
    };
    auto sts=[&](int buf){
#pragma unroll
        for(int j=0;j<2;j++){int i=tid+128*j,r=i>>2,cb=i&3;
            As[buf][r][cb*4+0]=to_tf32(ra[j].x);As[buf][r][cb*4+1]=to_tf32(ra[j].y);
            As[buf][r][cb*4+2]=to_tf32(ra[j].z);As[buf][r][cb*4+3]=to_tf32(ra[j].w);}
#pragma unroll
        for(int j=0;j<4;j++){int i=tid+128*j,r=i>>2,cb=i&3;
            Bs[buf][r][cb*4+0]=to_tf32(rb[j].x);Bs[buf][r][cb*4+1]=to_tf32(rb[j].y);
            Bs[buf][r][cb*4+2]=to_tf32(rb[j].z);Bs[buf][r][cb*4+3]=to_tf32(rb[j].w);}
    };
    ldg(0);sts(0);__syncthreads();
    const int nst=K/16;
    for(int s=0;s<nst;s++){
        const int cur=s&1;
        if(s+1<nst) ldg((s+1)*16);
#pragma unroll
        for(int kk=0;kk<2;kk++){
            const int kb=kk*8;
            uint32_t af[2][4];
#pragma unroll
            for(int mi=0;mi<2;mi++){int mr=wm*32+mi*16;
                af[mi][0]=__float_as_uint(As[cur][mr+g][kb+t]);
                af[mi][1]=__float_as_uint(As[cur][mr+g+8][kb+t]);
                af[mi][2]=__float_as_uint(As[cur][mr+g][kb+t+4]);
                af[mi][3]=__float_as_uint(As[cur][mr+g+8][kb+t+4]);}
            uint32_t bf[8][2];
#pragma unroll
            for(int ni=0;ni<8;ni++){int nr=wn*64+ni*8+g;
                bf[ni][0]=__float_as_uint(Bs[cur][nr][kb+t]);
                bf[ni][1]=__float_as_uint(Bs[cur][nr][kb+t+4]);}
#pragma unroll
            for(int mi=0;mi<2;mi++)
#pragma unroll
                for(int ni=0;ni<8;ni++) mma_tf32(acc[mi][ni],af[mi],bf[ni]);
        }
        if(s+1<nst) sts(cur^1);
        __syncthreads();
    }
#pragma unroll
    for(int mi=0;mi<2;mi++)
#pragma unroll
      for(int ni=0;ni<8;ni++){
        int row=wm*32+mi*16+g, col=n0+wn*64+ni*8+2*t;
        float b0=bias1[col],b1=bias1[col+1];
        float* p=C+(size_t)row*N+col;
        p[0]=acc[mi][ni][0]+b0; p[1]=acc[mi][ni][1]+b1;
        p=C+(size_t)(row+8)*N+col;
        p[0]=acc[mi][ni][2]+b0; p[1]=acc[mi][ni][3]+b1;
      }
}

// ---- softmax over S per batch row (4 partial slabs) ----
__global__ void __launch_bounds__(256) softmax_kernel(const float* __restrict__ part,float* __restrict__ attn){
    __shared__ float sc[NS];
    __shared__ float wred[8];
    const int b=blockIdx.x,tid=threadIdx.x,lane=tid&31,warp=tid>>5;
    float lmax=-1e30f;
    for(int s=tid;s<NS;s+=256){
        float v=0.f;
#pragma unroll
        for(int p=0;p<4;p++) v+=part[(size_t)p*(NB*NS)+b*NS+s];
        sc[s]=v; lmax=fmaxf(lmax,v);
    }
#pragma unroll
    for(int o=16;o>0;o>>=1) lmax=fmaxf(lmax,__shfl_xor_sync(0xffffffffu,lmax,o));
    if(lane==0) wred[warp]=lmax;
    __syncthreads();
    float m=wred[0];
#pragma unroll
    for(int w=1;w<8;w++) m=fmaxf(m,wred[w]);
    __syncthreads();
    float lsum=0.f;
    for(int s=tid;s<NS;s+=256){float e=expf(sc[s]-m);sc[s]=e;lsum+=e;}
#pragma unroll
    for(int o=16;o>0;o>>=1) lsum+=__shfl_xor_sync(0xffffffffu,lsum,o);
    if(lane==0) wred[warp]=lsum;
    __syncthreads();
    float tot=0.f;
#pragma unroll
    for(int w=0;w<8;w++) tot+=wred[w];
    const float inv=1.f/tot;
    for(int s=tid;s<NS;s+=256) attn[b*NS+s]=sc[s]*inv;
}

// ---- context from bf16 enc: xh0[b][1024+e] = sum_s attn[b,s]*encb[b,s,e] ----
__global__ void __launch_bounds__(128) context_kernel(const float* __restrict__ attn,
    const __nv_bfloat16* __restrict__ encb,float* __restrict__ xh0){
    __shared__ float aw[NS];
    const int b=blockIdx.x, p=blockIdx.y*128+threadIdx.x;  // bf162 pair index 0..511
    for(int s=threadIdx.x;s<NS;s+=128) aw[s]=attn[b*NS+s];
    __syncthreads();
    const uint32_t* ep=reinterpret_cast<const uint32_t*>(encb+(size_t)b*NS*1024)+p;
    float a0=0.f,a1=0.f;
#pragma unroll 4
    for(int s=0;s<NS;s++){
        uint32_t u=ep[(size_t)s*512];
        __nv_bfloat162 v=*reinterpret_cast<__nv_bfloat162*>(&u);
        float w=aw[s];
        a0+=w*__bfloat162float(v.x);
        a1+=w*__bfloat162float(v.y);
    }
    xh0[b*3072+1024+2*p]=a0;
    xh0[b*3072+1024+2*p+1]=a1;
}

extern "C" void kernel_launch(void* const* d_in,const int* in_sizes,int n_in,
                              void* d_out,int out_size){
    const int*   step = (const int*)  d_in[0];
    const float* h0   = (const float*)d_in[1];
    const float* c0   = (const float*)d_in[2];
    const float* enc  = (const float*)d_in[3];
    const float* emb  = (const float*)d_in[4];
    const float* Wah  = (const float*)d_in[5];
    const float* bah  = (const float*)d_in[6];
    const float* Wae  = (const float*)d_in[7];
    const float* bae  = (const float*)d_in[8];
    const float* va   = (const float*)d_in[9];
    const float* Wih0 = (const float*)d_in[11];
    const float* Whh0 = (const float*)d_in[12];
    const float* bih0 = (const float*)d_in[13];
    const float* bhh0 = (const float*)d_in[14];
    const float* Wih1 = (const float*)d_in[15];
    const float* Whh1 = (const float*)d_in[16];
    const float* bih1 = (const float*)d_in[17];
    const float* bhh1 = (const float*)d_in[18];
    const float* Wout = (const float*)d_in[19];
    const float* bout = (const float*)d_in[20];
    float* out=(float*)d_out;

    float *q,*part,*xh0,*xh1,*h2,*sk;
    __nv_bfloat16 *encb,*waeb;
    cudaGetSymbolAddress((void**)&q,g_q);
    cudaGetSymbolAddress((void**)&part,g_part);
    cudaGetSymbolAddress((void**)&xh0,g_xh0);
    cudaGetSymbolAddress((void**)&xh1,g_xh1);
    cudaGetSymbolAddress((void**)&h2,g_h2);
    cudaGetSymbolAddress((void**)&sk,g_sk);
    cudaGetSymbolAddress((void**)&encb,g_encb);
    cudaGetSymbolAddress((void**)&waeb,g_waeb);

    cudaFuncSetAttribute(score_kernel,cudaFuncAttributeMaxDynamicSharedMemorySize,SC_SMEM);

    // pre-convert enc + Wae to bf16
    cvt_bf16_kernel<<<8192,256>>>(enc,encb,(NB*NS*1024)/4);
    cvt_bf16_kernel<<<1024,256>>>(Wae,waeb,(1024*1024)/4);
    stage_kernel<<<64,256>>>(step,emb,h0,xh0,xh1);
    // q = h0[1]@Wah^T + bah + bae   (split-K 8)
    gemm_sk<<<dim3(8,SK),128>>>(h0+64*1024,Wah,Wah,sk,1024,1024,1024,1024/SK);
    reduce_q_kernel<<<256,256>>>(sk,bah,bae,q);
    // fused attention scores
    score_kernel<<<dim3(4,512),256,SC_SMEM>>>(encb,waeb,q,va,part);
    softmax_kernel<<<64,256>>>(part,out+OUT_ATT);
    context_kernel<<<dim3(64,4),128>>>(out+OUT_ATT,encb,xh0);
    // layer 0: [x|h0[0]] @ [Wih0|Whh0]^T  (K=3072, split-K 8) -> h1 into xh1 (stride 2048)
    gemm_sk<<<dim3(32,SK),128>>>(xh0,Wih0,Whh0,sk,4096,2048,3072,3072/SK);
    lstm_red_kernel<<<64,256>>>(sk,bih0,bhh0,c0,out+OUT_H,out+OUT_C,xh1,2048);
    // layer 1: [h1|h0[1]] @ [Wih1|Whh1]^T  (K=2048, split-K 8) -> h2 (stride 1024)
    gemm_sk<<<dim3(32,SK),128>>>(xh1,Wih1,Whh1,sk,4096,1024,2048,2048/SK);
    lstm_red_kernel<<<64,256>>>(sk,bih1,bhh1,c0+64*1024,out+OUT_H+64*1024,out+OUT_C+64*1024,h2,1024);
    // logits
    gemm_tf32_kernel<<<250,128>>>(h2,Wout,out,64,32000,1024,bout);
}

// round 11
// speedup vs baseline: 3.6149x; 1.0340x over previous
#include <cuda_runtime.h>
#include <cuda_bf16.h>
#include <stdint.h>
#include <math.h>

#define NB 64
#define NS 1024
#define NV 32000
#define NH 1024
// out: logits[64*32000] | h_new[2*64*1024] | c_new[2*64*1024] | attn[64*1024]
#define OUT_H   (NB*NV)
#define OUT_C   (OUT_H + 2*NB*NH)
#define OUT_ATT (OUT_C + 2*NB*NH)
#define SK 8            // K-splits for skinny GEMMs

__device__ float g_q[NB*1024];
__device__ float g_part[4*NB*NS];
__device__ float g_xh0[NB*3072];      // [emb | context | h0[0]]
__device__ float g_xh1[NB*2048];      // [h1 | h0[1]]
__device__ float g_h2[NB*NH];
__device__ float g_sk[SK*NB*4096];    // split-K partials (8 MB)
__device__ __nv_bfloat16 g_encb[(size_t)NB*NS*1024];
__device__ __nv_bfloat16 g_waeb[1024*1024];

__device__ __forceinline__ float fast_tanh(float x){float y;asm("tanh.approx.f32 %0,%1;":"=f"(y):"f"(x));return y;}
__device__ __forceinline__ float to_tf32(float x){uint32_t u;asm("cvt.rna.tf32.f32 %0,%1;":"=r"(u):"f"(x));return __uint_as_float(u);}
__device__ __forceinline__ float sigf(float x){return 1.f/(1.f+expf(-x));}

__device__ __forceinline__ uint32_t smem_u32(const void* p){
    uint32_t a; asm("{ .reg .u64 t; cvta.to.shared.u64 t, %1; cvt.u32.u64 %0, t; }":"=r"(a):"l"(p)); return a;
}
__device__ __forceinline__ void cp_async16(uint32_t dst,const void* src){
    asm volatile("cp.async.cg.shared.global [%0], [%1], 16;\n"::"r"(dst),"l"(src):"memory");
}
__device__ __forceinline__ void cp_commit(){
    asm volatile("cp.async.commit_group;\n":::"memory");
}

__device__ __forceinline__ void mma_tf32(float* c,const uint32_t* a,const uint32_t* b){
    asm volatile("mma.sync.aligned.m16n8k8.row.col.f32.tf32.tf32.f32 "
        "{%0,%1,%2,%3},{%4,%5,%6,%7},{%8,%9},{%0,%1,%2,%3};\n"
        : "+f"(c[0]),"+f"(c[1]),"+f"(c[2]),"+f"(c[3])
        : "r"(a[0]),"r"(a[1]),"r"(a[2]),"r"(a[3]),"r"(b[0]),"r"(b[1]));
}
__device__ __forceinline__ void mma_bf16(float* c,const uint32_t* a,const uint32_t* b){
    asm volatile("mma.sync.aligned.m16n8k16.row.col.f32.bf16.bf16.f32 "
        "{%0,%1,%2,%3},{%4,%5,%6,%7},{%8,%9},{%0,%1,%2,%3};\n"
        : "+f"(c[0]),"+f"(c[1]),"+f"(c[2]),"+f"(c[3])
        : "r"(a[0]),"r"(a[1]),"r"(a[2]),"r"(a[3]),"r"(b[0]),"r"(b[1]));
}
#define LDSM4(r0,r1,r2,r3,addr) \
    asm volatile("ldmatrix.sync.aligned.m8n8.x4.shared.b16 {%0,%1,%2,%3},[%4];" \
        : "=r"(r0),"=r"(r1),"=r"(r2),"=r"(r3) : "r"(addr))

// ---- fp32 -> bf16 conversion ----
__global__ void cvt_bf16_kernel(const float* __restrict__ in,__nv_bfloat16* __restrict__ out,int n4){
    int i=blockIdx.x*blockDim.x+threadIdx.x;
    const float4* in4=reinterpret_cast<const float4*>(in);
    uint2* out2=reinterpret_cast<uint2*>(out);
    for(;i<n4;i+=gridDim.x*blockDim.x){
        float4 v=in4[i];
        __nv_bfloat162 lo=__floats2bfloat162_rn(v.x,v.y);
        __nv_bfloat162 hi=__floats2bfloat162_rn(v.z,v.w);
        uint2 u; u.x=*reinterpret_cast<uint32_t*>(&lo); u.y=*reinterpret_cast<uint32_t*>(&hi);
        out2[i]=u;
    }
}

// ---- embed + stage h0 rows into concat buffers ----
__global__ void stage_kernel(const int* __restrict__ step,const float* __restrict__ emb,
    const float* __restrict__ h0,float* __restrict__ xh0,float* __restrict__ xh1){
    int b=blockIdx.x; int idx=step[b];
    for(int j=threadIdx.x;j<1024;j+=256){
        xh0[b*3072+j]=emb[(size_t)idx*1024+j];
        xh0[b*3072+2048+j]=h0[b*1024+j];          // h0 layer0
        xh1[b*2048+1024+j]=h0[65536+b*1024+j];    // h0 layer1
    }
}

// ===========================================================================
// Split-K skinny GEMM: part[z][64][N] = A[64, zKc:(z+1)Kc] @ Bcat[N, ...]^T
// ===========================================================================
__global__ void __launch_bounds__(128) gemm_sk(
    const float* __restrict__ A,const float* __restrict__ B1,const float* __restrict__ B2,
    float* __restrict__ part,int N,int K1,int K,int Kc)
{
    __shared__ float As[2][64][20];
    __shared__ float Bs[2][128][20];
    const int tid=threadIdx.x,lane=tid&31,warp=tid>>5;
    const int wm=warp&1,wn=warp>>1,g=lane>>2,t=lane&3;
    const int n0=blockIdx.x*128;
    const int z=blockIdx.y, kbase=z*Kc, K2=K-K1;
    float acc[2][8][4];
#pragma unroll
    for(int i=0;i<2;i++)
#pragma unroll
      for(int j=0;j<8;j++)
#pragma unroll
        for(int k=0;k<4;k++) acc[i][j][k]=0.f;
    float4 ra[2],rb[4];
    auto ldg=[&](int k0){
        int kg=kbase+k0;
#pragma unroll
        for(int j=0;j<2;j++){int i=tid+128*j,r=i>>2,cb=i&3;
            ra[j]=*reinterpret_cast<const float4*>(A+(size_t)r*K+kg+cb*4);}
#pragma unroll
        for(int j=0;j<4;j++){int i=tid+128*j,r=i>>2,cb=i&3;
            int kk=kg+cb*4;
            const float* src=(kk<K1)? B1+(size_t)(n0+r)*K1+kk : B2+(size_t)(n0+r)*K2+(kk-K1);
            rb[j]=*reinterpret_cast<const float4*>(src);}
    };
    auto sts=[&](int buf){
#pragma unroll
        for(int j=0;j<2;j++){int i=tid+128*j,r=i>>2,cb=i&3;
            As[buf][r][cb*4+0]=to_tf32(ra[j].x);As[buf][r][cb*4+1]=to_tf32(ra[j].y);
            As[buf][r][cb*4+2]=to_tf32(ra[j].z);As[buf][r][cb*4+3]=to_tf32(ra[j].w);}
#pragma unroll
        for(int j=0;j<4;j++){int i=tid+128*j,r=i>>2,cb=i&3;
            Bs[buf][r][cb*4+0]=to_tf32(rb[j].x);Bs[buf][r][cb*4+1]=to_tf32(rb[j].y);
            Bs[buf][r][cb*4+2]=to_tf32(rb[j].z);Bs[buf][r][cb*4+3]=to_tf32(rb[j].w);}
    };
    ldg(0);sts(0);__syncthreads();
    const int nst=Kc/16;
    for(int s=0;s<nst;s++){
        const int cur=s&1;
        if(s+1<nst) ldg((s+1)*16);
#pragma unroll
        for(int kk=0;kk<2;kk++){
            const int kb=kk*8;
            uint32_t af[2][4];
#pragma unroll
            for(int mi=0;mi<2;mi++){int mr=wm*32+mi*16;
                af[mi][0]=__float_as_uint(As[cur][mr+g][kb+t]);
                af[mi][1]=__float_as_uint(As[cur][mr+g+8][kb+t]);
                af[mi][2]=__float_as_uint(As[cur][mr+g][kb+t+4]);
                af[mi][3]=__float_as_uint(As[cur][mr+g+8][kb+t+4]);}
            uint32_t bf[8][2];
#pragma unroll
            for(int ni=0;ni<8;ni++){int nr=wn*64+ni*8+g;
                bf[ni][0]=__float_as_uint(Bs[cur][nr][kb+t]);
                bf[ni][1]=__float_as_uint(Bs[cur][nr][kb+t+4]);}
#pragma unroll
            for(int mi=0;mi<2;mi++)
#pragma unroll
                for(int ni=0;ni<8;ni++) mma_tf32(acc[mi][ni],af[mi],bf[ni]);
        }
        if(s+1<nst) sts(cur^1);
        __syncthreads();
    }
    float* out=part+(size_t)z*64*N;
#pragma unroll
    for(int mi=0;mi<2;mi++)
#pragma unroll
      for(int ni=0;ni<8;ni++){
        int row=wm*32+mi*16+g, col=n0+wn*64+ni*8+2*t;
        float* p=out+(size_t)row*N+col;
        p[0]=acc[mi][ni][0]; p[1]=acc[mi][ni][1];
        p=out+(size_t)(row+8)*N+col;
        p[0]=acc[mi][ni][2]; p[1]=acc[mi][ni][3];
      }
}

// ---- q = sum_z part + bah + bae ----
__global__ void reduce_q_kernel(const float* __restrict__ part,const float* __restrict__ b1,
    const float* __restrict__ b2,float* __restrict__ q){
    int i=blockIdx.x*256+threadIdx.x;
    int n=i&1023;
    float v=b1[n]+b2[n];
#pragma unroll
    for(int z=0;z<SK;z++) v+=part[(size_t)z*65536+i];
    q[i]=v;
}

// ---- LSTM from split-K partials ----
__global__ void __launch_bounds__(256) lstm_red_kernel(const float* __restrict__ part,
    const float* __restrict__ bi,const float* __restrict__ bh,
    const float* __restrict__ cprev,float* __restrict__ hout,float* __restrict__ cout,
    float* __restrict__ hscr,int hstride){
    const int b=blockIdx.x;
    for(int j=threadIdx.x;j<1024;j+=256){
        float gsum[4];
#pragma unroll
        for(int gi2=0;gi2<4;gi2++){
            int col=gi2*1024+j;
            float v=bi[col]+bh[col];
#pragma unroll
            for(int z=0;z<SK;z++) v+=part[(size_t)z*262144+b*4096+col];
            gsum[gi2]=v;
        }
        float c=sigf(gsum[1])*cprev[b*1024+j]+sigf(gsum[0])*tanhf(gsum[2]);
        float h=sigf(gsum[3])*tanhf(c);
        hout[b*1024+j]=h; cout[b*1024+j]=c; hscr[(size_t)b*hstride+j]=h;
    }
}

// ===========================================================================
// Fused attention-score GEMM (bf16 mma + cp.async, 6 stages, 2 chunks/barrier)
// ===========================================================================
#define SC_STAGE_BYTES 24576
#define SC_NSTAGE 6
#define SC_SMEM (SC_NSTAGE*SC_STAGE_BYTES)   // 147456

__global__ void __launch_bounds__(256,1) score_kernel(
    const __nv_bfloat16* __restrict__ encb,const __nv_bfloat16* __restrict__ waeb,
    const float* __restrict__ q,const float* __restrict__ va,float* __restrict__ part)
{
    extern __shared__ __align__(128) char dyn[];
    __shared__ float red[128][4];
    __shared__ float2 qa[256];

    const uint32_t base=smem_u32(dyn);
    const int tid=threadIdx.x,lane=tid&31,warp=tid>>5;
    const int wm=warp&1,wn=warp>>1;
    const int g=lane>>2,t=lane&3;
    const int m0=blockIdx.y*128, n0=blockIdx.x*256;
    const int b=blockIdx.y>>3;

    qa[tid]=make_float2(q[b*1024+n0+tid], va[n0+tid]);

    const int rA=wm*64+(lane&15);
    const int hiA=lane>>4;
    const uint32_t sxA=((uint32_t)rA>>1)&3;
    const int rB=wn*64+(lane&7)+((lane>>4)<<3);
    const int hiB=(lane>>3)&1;
    const uint32_t sxB=((uint32_t)rB>>1)&3;
    uint32_t aoff[2],boff[2];
#pragma unroll
    for(int kk=0;kk<2;kk++){
        aoff[kk]=(uint32_t)rA*64+((((uint32_t)(2*kk+hiA))^sxA)<<4);
        boff[kk]=8192u+(uint32_t)rB*64+((((uint32_t)(2*kk+hiB))^sxB)<<4);
    }

    float acc[4][8][4];
#pragma unroll
    for(int i=0;i<4;i++)
#pragma unroll
      for(int j=0;j<8;j++)
#pragma unroll
        for(int k=0;k<4;k++) acc[i][j][k]=0.f;

    auto fill=[&](int s,int k0){
        const uint32_t sbase=base+(uint32_t)s*SC_STAGE_BYTES;
#pragma unroll
        for(int j=0;j<2;j++){
            int idx=tid+256*j; int r=idx>>2, seg=idx&3;
            uint32_t dst=sbase+(uint32_t)r*64+((((uint32_t)seg)^(((uint32_t)r>>1)&3))<<4);
            cp_async16(dst, encb+(size_t)(m0+r)*1024+k0+seg*8);
        }
#pragma unroll
        for(int j=0;j<4;j++){
            int idx=tid+256*j; int r=idx>>2, seg=idx&3;
            uint32_t dst=sbase+8192u+(uint32_t)r*64+((((uint32_t)seg)^(((uint32_t)r>>1)&3))<<4);
            cp_async16(dst, waeb+(size_t)(n0+r)*1024+k0+seg*8);
        }
        cp_commit();
    };

    auto consume=[&](int stage){
        const uint32_t sb2=base+(uint32_t)stage*SC_STAGE_BYTES;
#pragma unroll
        for(int kk=0;kk<2;kk++){
            uint32_t af[4][4];
#pragma unroll
            for(int mi=0;mi<4;mi++)
                LDSM4(af[mi][0],af[mi][1],af[mi][2],af[mi][3], sb2+aoff[kk]+(uint32_t)mi*1024);
            uint32_t bf[8][2];
#pragma unroll
            for(int p=0;p<4;p++)
                LDSM4(bf[2*p][0],bf[2*p][1],bf[2*p+1][0],bf[2*p+1][1], sb2+boff[kk]+(uint32_t)p*1024);
#pragma unroll
            for(int mi=0;mi<4;mi++)
#pragma unroll
                for(int ni=0;ni<8;ni++) mma_bf16(acc[mi][ni],af[mi],bf[ni]);
        }
    };

    // prefetch 4 chunks
    fill(0,0); fill(1,32); fill(2,64); fill(3,96);
#pragma unroll 1
    for(int i=0;i<32;i+=2){
        if(i<30){ asm volatile("cp.async.wait_group 2;\n":::"memory"); }
        else    { asm volatile("cp.async.wait_group 0;\n":::"memory"); }
        __syncthreads();
        consume(i%SC_NSTAGE);
        if(i+4<32) fill((i+4)%SC_NSTAGE,(i+4)*32);
        consume((i+1)%SC_NSTAGE);
        if(i+5<32) fill((i+5)%SC_NSTAGE,(i+5)*32);
    }

    float rs[4][2];
#pragma unroll
    for(int mi=0;mi<4;mi++){rs[mi][0]=0.f;rs[mi][1]=0.f;}
#pragma unroll
    for(int ni=0;ni<8;ni++){
        int col=wn*64+ni*8+2*t;
        float2 qa0=qa[col], qa1=qa[col+1];
#pragma unroll
        for(int mi=0;mi<4;mi++){
            rs[mi][0]+=qa0.y*fast_tanh(qa0.x+acc[mi][ni][0])+qa1.y*fast_tanh(qa1.x+acc[mi][ni][1]);
            rs[mi][1]+=qa0.y*fast_tanh(qa0.x+acc[mi][ni][2])+qa1.y*fast_tanh(qa1.x+acc[mi][ni][3]);
        }
    }
#pragma unroll
    for(int o=1;o<4;o<<=1)
#pragma unroll
      for(int mi=0;mi<4;mi++){
        rs[mi][0]+=__shfl_xor_sync(0xffffffffu,rs[mi][0],o);
        rs[mi][1]+=__shfl_xor_sync(0xffffffffu,rs[mi][1],o);
      }
    if(t==0)
#pragma unroll
      for(int mi=0;mi<4;mi++){
        red[wm*64+mi*16+g][wn]=rs[mi][0];
        red[wm*64+mi*16+8+g][wn]=rs[mi][1];
      }
    __syncthreads();
    if(tid<128)
        part[(size_t)blockIdx.x*(NB*NS)+m0+tid]=(red[tid][0]+red[tid][1])+(red[tid][2]+red[tid][3]);
}

// ---- full-size non-split GEMM (logits): C[64,N] = A@B^T + bias ----
__global__ void __launch_bounds__(128) gemm_tf32_kernel(
    const float* __restrict__ A,const float* __restrict__ Bm,float* __restrict__ C,
    int M,int N,int K,const float* __restrict__ bias1)
{
    __shared__ float As[2][64][20];
    __shared__ float Bs[2][128][20];
    const int tid=threadIdx.x,lane=tid&31,warp=tid>>5;
    const int wm=warp&1,wn=warp>>1,g=lane>>2,t=lane&3;
    const int n0=blockIdx.x*128;
    float acc[2][8][4];
#pragma unroll
    for(int i=0;i<2;i++)
#pragma unroll
      for(int j=0;j<8;j++)
#pragma unroll
        for(int k=0;k<4;k++) acc[i][j][k]=0.f;
    float4 ra[2],rb[4];
    auto ldg=[&](int k0){
#pragma unroll
        for(int j=0;j<2;j++){int i=tid+128*j,r=i>>2,cb=i&3;
            ra[j]=*reinterpret_cast<const float4*>(A+(size_t)r*K+k0+cb*4);}
#pragma unroll
        for(int j=0;j<4;j++){int i=tid+128*j,r=i>>2,cb=i&3;
            rb[j]=*reinterpret_cast<const float4*>(Bm+(size_t)(n0+r)*K+k0+cb*4);}
    };
    auto sts=[&](int buf){
#pragma unroll
        for(int j=0;j<2;j++){int i=tid+128*j,r=i>>2,cb=i&3;
            As[buf][r][cb*4+0]=to_tf32(ra[j].x);As[buf][r][cb*4+1]=to_tf32(ra[j].y);
            As[buf][r][cb*4+2]=to_tf32(ra[j].z);As[buf][r][cb*4+3]=to_tf32(ra[j].w);}
#pragma unroll
        for(int j=0;j<4;j++){int i=tid+128*j,r=i>>2,cb=i&3;
            Bs[buf][r][cb*4+0]=to_tf32(rb[j].x);Bs[buf][r][cb*4+1]=to_tf32(rb[j].y);
            Bs[buf][r][cb*4+2]=to_tf32(rb[j].z);Bs[buf][r][cb*4+3]=to_tf32(rb[j].w);}
    };
    ldg(0);sts(0);__syncthreads();
    const int nst=K/16;
    for(int s=0;s<nst;s++){
        const int cur=s&1;
        if(s+1<nst) ldg((s+1)*16);
#pragma unroll
        for(int kk=0;kk<2;kk++){
            const int kb=kk*8;
            uint32_t af[2][4];
#pragma unroll
            for(int mi=0;mi<2;mi++){int mr=wm*32+mi*16;
                af[mi][0]=__float_as_uint(As[cur][mr+g][kb+t]);
                af[mi][1]=__float_as_uint(As[cur][mr+g+8][kb+t]);
                af[mi][2]=__float_as_uint(As[cur][mr+g][kb+t+4]);
                af[mi][3]=__float_as_uint(As[cur][mr+g+8][kb+t+4]);}
            uint32_t bf[8][2];
#pragma unroll
            for(int ni=0;ni<8;ni++){int nr=wn*64+ni*8+g;
                bf[ni][0]=__float_as_uint(Bs[cur][nr][kb+t]);
                bf[ni][1]=__float_as_uint(Bs[cur][nr][kb+t+4]);}
#pragma unroll
            for(int mi=0;mi<2;mi++)
#pragma unroll
                for(int ni=0;ni<8;ni++) mma_tf32(acc[mi][ni],af[mi],bf[ni]);
        }
        if(s+1<nst) sts(cur^1);
        __syncthreads();
    }
#pragma unroll
    for(int mi=0;mi<2;mi++)
#pragma unroll
      for(int ni=0;ni<8;ni++){
        int row=wm*32+mi*16+g, col=n0+wn*64+ni*8+2*t;
        float b0=bias1[col],b1=bias1[col+1];
        float* p=C+(size_t)row*N+col;
        p[0]=acc[mi][ni][0]+b0; p[1]=acc[mi][ni][1]+b1;
        p=C+(size_t)(row+8)*N+col;
        p[0]=acc[mi][ni][2]+b0; p[1]=acc[mi][ni][3]+b1;
      }
}

// ---- softmax over S per batch row (4 partial slabs) ----
__global__ void __launch_bounds__(256) softmax_kernel(const float* __restrict__ part,float* __restrict__ attn){
    __shared__ float sc[NS];
    __shared__ float wred[8];
    const int b=blockIdx.x,tid=threadIdx.x,lane=tid&31,warp=tid>>5;
    float lmax=-1e30f;
    for(int s=tid;s<NS;s+=256){
        float v=0.f;
#pragma unroll
        for(int p=0;p<4;p++) v+=part[(size_t)p*(NB*NS)+b*NS+s];
        sc[s]=v; lmax=fmaxf(lmax,v);
    }
#pragma unroll
    for(int o=16;o>0;o>>=1) lmax=fmaxf(lmax,__shfl_xor_sync(0xffffffffu,lmax,o));
    if(lane==0) wred[warp]=lmax;
    __syncthreads();
    float m=wred[0];
#pragma unroll
    for(int w=1;w<8;w++) m=fmaxf(m,wred[w]);
    __syncthreads();
    float lsum=0.f;
    for(int s=tid;s<NS;s+=256){float e=expf(sc[s]-m);sc[s]=e;lsum+=e;}
#pragma unroll
    for(int o=16;o>0;o>>=1) lsum+=__shfl_xor_sync(0xffffffffu,lsum,o);
    if(lane==0) wred[warp]=lsum;
    __syncthreads();
    float tot=0.f;
#pragma unroll
    for(int w=0;w<8;w++) tot+=wred[w];
    const float inv=1.f/tot;
    for(int s=tid;s<NS;s+=256) attn[b*NS+s]=sc[s]*inv;
}

// ---- context from bf16 enc ----
__global__ void __launch_bounds__(128) context_kernel(const float* __restrict__ attn,
    const __nv_bfloat16* __restrict__ encb,float* __restrict__ xh0){
    __shared__ float aw[NS];
    const int b=blockIdx.x, p=blockIdx.y*128+threadIdx.x;
    for(int s=threadIdx.x;s<NS;s+=128) aw[s]=attn[b*NS+s];
    __syncthreads();
    const uint32_t* ep=reinterpret_cast<const uint32_t*>(encb+(size_t)b*NS*1024)+p;
    float a0=0.f,a1=0.f;
#pragma unroll 4
    for(int s=0;s<NS;s++){
        uint32_t u=ep[(size_t)s*512];
        __nv_bfloat162 v=*reinterpret_cast<__nv_bfloat162*>(&u);
        float w=aw[s];
        a0+=w*__bfloat162float(v.x);
        a1+=w*__bfloat162float(v.y);
    }
    xh0[b*3072+1024+2*p]=a0;
    xh0[b*3072+1024+2*p+1]=a1;
}

extern "C" void kernel_launch(void* const* d_in,const int* in_sizes,int n_in,
                              void* d_out,int out_size){
    const int*   step = (const int*)  d_in[0];
    const float* h0   = (const float*)d_in[1];
    const float* c0   = (const float*)d_in[2];
    const float* enc  = (const float*)d_in[3];
    const float* emb  = (const float*)d_in[4];
    const float* Wah  = (const float*)d_in[5];
    const float* bah  = (const float*)d_in[6];
    const float* Wae  = (const float*)d_in[7];
    const float* bae  = (const float*)d_in[8];
    const float* va   = (const float*)d_in[9];
    const float* Wih0 = (const float*)d_in[11];
    const float* Whh0 = (const float*)d_in[12];
    const float* bih0 = (const float*)d_in[13];
    const float* bhh0 = (const float*)d_in[14];
    const float* Wih1 = (const float*)d_in[15];
    const float* Whh1 = (const float*)d_in[16];
    const float* bih1 = (const float*)d_in[17];
    const float* bhh1 = (const float*)d_in[18];
    const float* Wout = (const float*)d_in[19];
    const float* bout = (const float*)d_in[20];
    float* out=(float*)d_out;

    float *q,*part,*xh0,*xh1,*h2,*sk;
    __nv_bfloat16 *encb,*waeb;
    cudaGetSymbolAddress((void**)&q,g_q);
    cudaGetSymbolAddress((void**)&part,g_part);
    cudaGetSymbolAddress((void**)&xh0,g_xh0);
    cudaGetSymbolAddress((void**)&xh1,g_xh1);
    cudaGetSymbolAddress((void**)&h2,g_h2);
    cudaGetSymbolAddress((void**)&sk,g_sk);
    cudaGetSymbolAddress((void**)&encb,g_encb);
    cudaGetSymbolAddress((void**)&waeb,g_waeb);

    cudaFuncSetAttribute(score_kernel,cudaFuncAttributeMaxDynamicSharedMemorySize,SC_SMEM);

    cvt_bf16_kernel<<<8192,256>>>(enc,encb,(NB*NS*1024)/4);
    cvt_bf16_kernel<<<1024,256>>>(Wae,waeb,(1024*1024)/4);
    stage_kernel<<<64,256>>>(step,emb,h0,xh0,xh1);
    gemm_sk<<<dim3(8,SK),128>>>(h0+64*1024,Wah,Wah,sk,1024,1024,1024,1024/SK);
    reduce_q_kernel<<<256,256>>>(sk,bah,bae,q);
    score_kernel<<<dim3(4,512),256,SC_SMEM>>>(encb,waeb,q,va,part);
    softmax_kernel<<<64,256>>>(part,out+OUT_ATT);
    context_kernel<<<dim3(64,4),128>>>(out+OUT_ATT,encb,xh0);
    gemm_sk<<<dim3(32,SK),128>>>(xh0,Wih0,Whh0,sk,4096,2048,3072,3072/SK);
    lstm_red_kernel<<<64,256>>>(sk,bih0,bhh0,c0,out+OUT_H,out+OUT_C,xh1,2048);
    gemm_sk<<<dim3(32,SK),128>>>(xh1,Wih1,Whh1,sk,4096,1024,2048,2048/SK);
    lstm_red_kernel<<<64,256>>>(sk,bih1,bhh1,c0+64*1024,out+OUT_H+64*1024,out+OUT_C+64*1024,h2,1024);
    gemm_tf32_kernel<<<250,128>>>(h2,Wout,out,64,32000,1024,bout);
}

// round 12
// speedup vs baseline: 3.6639x; 1.0136x over previous
#include <cuda_runtime.h>
#include <cuda_bf16.h>
#include <stdint.h>
#include <math.h>

#define NB 64
#define NS 1024
#define NV 32000
#define NH 1024
// out: logits[64*32000] | h_new[2*64*1024] | c_new[2*64*1024] | attn[64*1024]
#define OUT_H   (NB*NV)
#define OUT_C   (OUT_H + 2*NB*NH)
#define OUT_ATT (OUT_C + 2*NB*NH)
#define SK 8            // K-splits for skinny GEMMs

__device__ float g_q[NB*1024];
__device__ float g_part[8*NB*NS];
__device__ float g_xh0[NB*3072];      // [emb | context | h0[0]]
__device__ float g_xh1[NB*2048];      // [h1 | h0[1]]
__device__ float g_h2[NB*NH];
__device__ float g_sk[SK*NB*4096];    // split-K partials (8 MB)
__device__ __nv_bfloat16 g_encb[(size_t)NB*NS*1024];
__device__ __nv_bfloat16 g_waeb[1024*1024];

__device__ __forceinline__ float fast_tanh(float x){float y;asm("tanh.approx.f32 %0,%1;":"=f"(y):"f"(x));return y;}
__device__ __forceinline__ float to_tf32(float x){uint32_t u;asm("cvt.rna.tf32.f32 %0,%1;":"=r"(u):"f"(x));return __uint_as_float(u);}
__device__ __forceinline__ float sigf(float x){return 1.f/(1.f+expf(-x));}

__device__ __forceinline__ uint32_t smem_u32(const void* p){
    uint32_t a; asm("{ .reg .u64 t; cvta.to.shared.u64 t, %1; cvt.u32.u64 %0, t; }":"=r"(a):"l"(p)); return a;
}
__device__ __forceinline__ void cp_async16(uint32_t dst,const void* src){
    asm volatile("cp.async.cg.shared.global [%0], [%1], 16;\n"::"r"(dst),"l"(src):"memory");
}
__device__ __forceinline__ void cp_commit(){
    asm volatile("cp.async.commit_group;\n":::"memory");
}

__device__ __forceinline__ void mma_tf32(float* c,const uint32_t* a,const uint32_t* b){
    asm volatile("mma.sync.aligned.m16n8k8.row.col.f32.tf32.tf32.f32 "
        "{%0,%1,%2,%3},{%4,%5,%6,%7},{%8,%9},{%0,%1,%2,%3};\n"
        : "+f"(c[0]),"+f"(c[1]),"+f"(c[2]),"+f"(c[3])
        : "r"(a[0]),"r"(a[1]),"r"(a[2]),"r"(a[3]),"r"(b[0]),"r"(b[1]));
}
__device__ __forceinline__ void mma_bf16(float* c,const uint32_t* a,const uint32_t* b){
    asm volatile("mma.sync.aligned.m16n8k16.row.col.f32.bf16.bf16.f32 "
        "{%0,%1,%2,%3},{%4,%5,%6,%7},{%8,%9},{%0,%1,%2,%3};\n"
        : "+f"(c[0]),"+f"(c[1]),"+f"(c[2]),"+f"(c[3])
        : "r"(a[0]),"r"(a[1]),"r"(a[2]),"r"(a[3]),"r"(b[0]),"r"(b[1]));
}
#define LDSM4(r0,r1,r2,r3,addr) \
    asm volatile("ldmatrix.sync.aligned.m8n8.x4.shared.b16 {%0,%1,%2,%3},[%4];" \
        : "=r"(r0),"=r"(r1),"=r"(r2),"=r"(r3) : "r"(addr))

// ---- fp32 -> bf16 conversion ----
__global__ void cvt_bf16_kernel(const float* __restrict__ in,__nv_bfloat16* __restrict__ out,int n4){
    int i=blockIdx.x*blockDim.x+threadIdx.x;
    const float4* in4=reinterpret_cast<const float4*>(in);
    uint2* out2=reinterpret_cast<uint2*>(out);
    for(;i<n4;i+=gridDim.x*blockDim.x){
        float4 v=in4[i];
        __nv_bfloat162 lo=__floats2bfloat162_rn(v.x,v.y);
        __nv_bfloat162 hi=__floats2bfloat162_rn(v.z,v.w);
        uint2 u; u.x=*reinterpret_cast<uint32_t*>(&lo); u.y=*reinterpret_cast<uint32_t*>(&hi);
        out2[i]=u;
    }
}

// ---- embed + stage h0 rows into concat buffers ----
__global__ void stage_kernel(const int* __restrict__ step,const float* __restrict__ emb,
    const float* __restrict__ h0,float* __restrict__ xh0,float* __restrict__ xh1){
    int b=blockIdx.x; int idx=step[b];
    for(int j=threadIdx.x;j<1024;j+=256){
        xh0[b*3072+j]=emb[(size_t)idx*1024+j];
        xh0[b*3072+2048+j]=h0[b*1024+j];
        xh1[b*2048+1024+j]=h0[65536+b*1024+j];
    }
}

// ===========================================================================
// Split-K skinny GEMM (tf32): part[z][64][N] = A[64,slice] @ Bcat^T
// ===========================================================================
__global__ void __launch_bounds__(128) gemm_sk(
    const float* __restrict__ A,const float* __restrict__ B1,const float* __restrict__ B2,
    float* __restrict__ part,int N,int K1,int K,int Kc)
{
    __shared__ float As[2][64][20];
    __shared__ float Bs[2][128][20];
    const int tid=threadIdx.x,lane=tid&31,warp=tid>>5;
    const int wm=warp&1,wn=warp>>1,g=lane>>2,t=lane&3;
    const int n0=blockIdx.x*128;
    const int z=blockIdx.y, kbase=z*Kc, K2=K-K1;
    float acc[2][8][4];
#pragma unroll
    for(int i=0;i<2;i++)
#pragma unroll
      for(int j=0;j<8;j++)
#pragma unroll
        for(int k=0;k<4;k++) acc[i][j][k]=0.f;
    float4 ra[2],rb[4];
    auto ldg=[&](int k0){
        int kg=kbase+k0;
#pragma unroll
        for(int j=0;j<2;j++){int i=tid+128*j,r=i>>2,cb=i&3;
            ra[j]=*reinterpret_cast<const float4*>(A+(size_t)r*K+kg+cb*4);}
#pragma unroll
        for(int j=0;j<4;j++){int i=tid+128*j,r=i>>2,cb=i&3;
            int kk=kg+cb*4;
            const float* src=(kk<K1)? B1+(size_t)(n0+r)*K1+kk : B2+(size_t)(n0+r)*K2+(kk-K1);
            rb[j]=*reinterpret_cast<const float4*>(src);}
    };
    auto sts=[&](int buf){
#pragma unroll
        for(int j=0;j<2;j++){int i=tid+128*j,r=i>>2,cb=i&3;
            As[buf][r][cb*4+0]=to_tf32(ra[j].x);As[buf][r][cb*4+1]=to_tf32(ra[j].y);
            As[buf][r][cb*4+2]=to_tf32(ra[j].z);As[buf][r][cb*4+3]=to_tf32(ra[j].w);}
#pragma unroll
        for(int j=0;j<4;j++){int i=tid+128*j,r=i>>2,cb=i&3;
            Bs[buf][r][cb*4+0]=to_tf32(rb[j].x);Bs[buf][r][cb*4+1]=to_tf32(rb[j].y);
            Bs[buf][r][cb*4+2]=to_tf32(rb[j].z);Bs[buf][r][cb*4+3]=to_tf32(rb[j].w);}
    };
    ldg(0);sts(0);__syncthreads();
    const int nst=Kc/16;
    for(int s=0;s<nst;s++){
        const int cur=s&1;
        if(s+1<nst) ldg((s+1)*16);
#pragma unroll
        for(int kk=0;kk<2;kk++){
            const int kb=kk*8;
            uint32_t af[2][4];
#pragma unroll
            for(int mi=0;mi<2;mi++){int mr=wm*32+mi*16;
                af[mi][0]=__float_as_uint(As[cur][mr+g][kb+t]);
                af[mi][1]=__float_as_uint(As[cur][mr+g+8][kb+t]);
                af[mi][2]=__float_as_uint(As[cur][mr+g][kb+t+4]);
                af[mi][3]=__float_as_uint(As[cur][mr+g+8][kb+t+4]);}
            uint32_t bf[8][2];
#pragma unroll
            for(int ni=0;ni<8;ni++){int nr=wn*64+ni*8+g;
                bf[ni][0]=__float_as_uint(Bs[cur][nr][kb+t]);
                bf[ni][1]=__float_as_uint(Bs[cur][nr][kb+t+4]);}
#pragma unroll
            for(int mi=0;mi<2;mi++)
#pragma unroll
                for(int ni=0;ni<8;ni++) mma_tf32(acc[mi][ni],af[mi],bf[ni]);
        }
        if(s+1<nst) sts(cur^1);
        __syncthreads();
    }
    float* out=part+(size_t)z*64*N;
#pragma unroll
    for(int mi=0;mi<2;mi++)
#pragma unroll
      for(int ni=0;ni<8;ni++){
        int row=wm*32+mi*16+g, col=n0+wn*64+ni*8+2*t;
        float* p=out+(size_t)row*N+col;
        p[0]=acc[mi][ni][0]; p[1]=acc[mi][ni][1];
        p=out+(size_t)(row+8)*N+col;
        p[0]=acc[mi][ni][2]; p[1]=acc[mi][ni][3];
      }
}

// ---- q = sum_z part + bah + bae ----
__global__ void reduce_q_kernel(const float* __restrict__ part,const float* __restrict__ b1,
    const float* __restrict__ b2,float* __restrict__ q){
    int i=blockIdx.x*256+threadIdx.x;
    int n=i&1023;
    float v=b1[n]+b2[n];
#pragma unroll
    for(int z=0;z<SK;z++) v+=part[(size_t)z*65536+i];
    q[i]=v;
}

// ---- LSTM from split-K partials ----
__global__ void __launch_bounds__(256) lstm_red_kernel(const float* __restrict__ part,
    const float* __restrict__ bi,const float* __restrict__ bh,
    const float* __restrict__ cprev,float* __restrict__ hout,float* __restrict__ cout,
    float* __restrict__ hscr,int hstride){
    const int b=blockIdx.x;
    for(int j=threadIdx.x;j<1024;j+=256){
        float gsum[4];
#pragma unroll
        for(int gi2=0;gi2<4;gi2++){
            int col=gi2*1024+j;
            float v=bi[col]+bh[col];
#pragma unroll
            for(int z=0;z<SK;z++) v+=part[(size_t)z*262144+b*4096+col];
            gsum[gi2]=v;
        }
        float c=sigf(gsum[1])*cprev[b*1024+j]+sigf(gsum[0])*tanhf(gsum[2]);
        float h=sigf(gsum[3])*tanhf(c);
        hout[b*1024+j]=h; cout[b*1024+j]=c; hscr[(size_t)b*hstride+j]=h;
    }
}

// ===========================================================================
// Fused attention-score GEMM v4: CTA 128x128, 8 warps (2Mx4N), warp 64x32,
// 6-stage cp.async, 2 CTAs/SM. part has 8 n-slabs of 128.
// ===========================================================================
#define SC_STAGE_BYTES 16384           // A 128*64 + B 128*64
#define SC_NSTAGE 6
#define SC_SMEM (SC_NSTAGE*SC_STAGE_BYTES)   // 98304

__global__ void __launch_bounds__(256,2) score_kernel(
    const __nv_bfloat16* __restrict__ encb,const __nv_bfloat16* __restrict__ waeb,
    const float* __restrict__ q,const float* __restrict__ va,float* __restrict__ part)
{
    extern __shared__ __align__(128) char dyn[];
    __shared__ float red[128][4];
    __shared__ float2 qa[128];

    const uint32_t base=smem_u32(dyn);
    const int tid=threadIdx.x,lane=tid&31,warp=tid>>5;
    const int wm=warp&1,wn=warp>>1;          // 2 (M) x 4 (N of 32)
    const int g=lane>>2,t=lane&3;
    const int m0=blockIdx.y*128, n0=blockIdx.x*128;
    const int b=blockIdx.y>>3;               // 8 m-tiles per batch row

    if(tid<128) qa[tid]=make_float2(q[b*1024+n0+tid], va[n0+tid]);

    // per-lane ldmatrix address components (64B rows, seg^(row>>1)&3 swizzle)
    const int rA=wm*64+(lane&15);
    const int hiA=lane>>4;
    const uint32_t sxA=((uint32_t)rA>>1)&3;
    const int rB=wn*32+(lane&7)+((lane>>4)<<3);
    const int hiB=(lane>>3)&1;
    const uint32_t sxB=((uint32_t)rB>>1)&3;
    uint32_t aoff[2],boff[2];
#pragma unroll
    for(int kk=0;kk<2;kk++){
        aoff[kk]=(uint32_t)rA*64+((((uint32_t)(2*kk+hiA))^sxA)<<4);
        boff[kk]=8192u+(uint32_t)rB*64+((((uint32_t)(2*kk+hiB))^sxB)<<4);
    }

    float acc[4][4][4];
#pragma unroll
    for(int i=0;i<4;i++)
#pragma unroll
      for(int j=0;j<4;j++)
#pragma unroll
        for(int k=0;k<4;k++) acc[i][j][k]=0.f;

    auto fill=[&](int s,int k0){
        const uint32_t sbase=base+(uint32_t)s*SC_STAGE_BYTES;
        {   // A: 128 rows x 4 segs = 512 cp over 256 thr (2 each)
#pragma unroll
            for(int j=0;j<2;j++){
                int idx=tid+256*j; int r=idx>>2, seg=idx&3;
                uint32_t dst=sbase+(uint32_t)r*64+((((uint32_t)seg)^(((uint32_t)r>>1)&3))<<4);
                cp_async16(dst, encb+(size_t)(m0+r)*1024+k0+seg*8);
            }
        }
        {   // B: 128 rows x 4 segs
#pragma unroll
            for(int j=0;j<2;j++){
                int idx=tid+256*j; int r=idx>>2, seg=idx&3;
                uint32_t dst=sbase+8192u+(uint32_t)r*64+((((uint32_t)seg)^(((uint32_t)r>>1)&3))<<4);
                cp_async16(dst, waeb+(size_t)(n0+r)*1024+k0+seg*8);
            }
        }
        cp_commit();
    };

    auto consume=[&](int stage){
        const uint32_t sb2=base+(uint32_t)stage*SC_STAGE_BYTES;
#pragma unroll
        for(int kk=0;kk<2;kk++){
            uint32_t af[4][4];
#pragma unroll
            for(int mi=0;mi<4;mi++)
                LDSM4(af[mi][0],af[mi][1],af[mi][2],af[mi][3], sb2+aoff[kk]+(uint32_t)mi*1024);
            uint32_t bf[4][2];
#pragma unroll
            for(int p=0;p<2;p++)
                LDSM4(bf[2*p][0],bf[2*p][1],bf[2*p+1][0],bf[2*p+1][1], sb2+boff[kk]+(uint32_t)p*1024);
#pragma unroll
            for(int mi=0;mi<4;mi++)
#pragma unroll
                for(int ni=0;ni<4;ni++) mma_bf16(acc[mi][ni],af[mi],bf[ni]);
        }
    };

    // prefetch 5 chunks
    fill(0,0); fill(1,32); fill(2,64); fill(3,96); fill(4,128);
#pragma unroll 1
    for(int i=0;i<32;i++){
        asm volatile("cp.async.wait_group 4;\n":::"memory");
        __syncthreads();
        consume(i%SC_NSTAGE);
        if(i+5<32) fill((i+5)%SC_NSTAGE,(i+5)*32);
        else cp_commit();
    }

    // epilogue: va*tanh(q + k), reduce over this CTA's 128 n-columns
    float rs[4][2];
#pragma unroll
    for(int mi=0;mi<4;mi++){rs[mi][0]=0.f;rs[mi][1]=0.f;}
#pragma unroll
    for(int ni=0;ni<4;ni++){
        int col=wn*32+ni*8+2*t;
        float2 qa0=qa[col], qa1=qa[col+1];
#pragma unroll
        for(int mi=0;mi<4;mi++){
            rs[mi][0]+=qa0.y*fast_tanh(qa0.x+acc[mi][ni][0])+qa1.y*fast_tanh(qa1.x+acc[mi][ni][1]);
            rs[mi][1]+=qa0.y*fast_tanh(qa0.x+acc[mi][ni][2])+qa1.y*fast_tanh(qa1.x+acc[mi][ni][3]);
        }
    }
#pragma unroll
    for(int o=1;o<4;o<<=1)
#pragma unroll
      for(int mi=0;mi<4;mi++){
        rs[mi][0]+=__shfl_xor_sync(0xffffffffu,rs[mi][0],o);
        rs[mi][1]+=__shfl_xor_sync(0xffffffffu,rs[mi][1],o);
      }
    if(t==0)
#pragma unroll
      for(int mi=0;mi<4;mi++){
        red[wm*64+mi*16+g][wn]=rs[mi][0];
        red[wm*64+mi*16+8+g][wn]=rs[mi][1];
      }
    __syncthreads();
    if(tid<128)
        part[(size_t)blockIdx.x*(NB*NS)+m0+tid]=(red[tid][0]+red[tid][1])+(red[tid][2]+red[tid][3]);
}

// ---- full-size non-split GEMM (logits): C[64,N] = A@B^T + bias ----
__global__ void __launch_bounds__(128) gemm_tf32_kernel(
    const float* __restrict__ A,const float* __restrict__ Bm,float* __restrict__ C,
    int M,int N,int K,const float* __restrict__ bias1)
{
    __shared__ float As[2][64][20];
    __shared__ float Bs[2][128][20];
    const int tid=threadIdx.x,lane=tid&31,warp=tid>>5;
    const int wm=warp&1,wn=warp>>1,g=lane>>2,t=lane&3;
    const int n0=blockIdx.x*128;
    float acc[2][8][4];
#pragma unroll
    for(int i=0;i<2;i++)
#pragma unroll
      for(int j=0;j<8;j++)
#pragma unroll
        for(int k=0;k<4;k++) acc[i][j][k]=0.f;
    float4 ra[2],rb[4];
    auto ldg=[&](int k0){
#pragma unroll
        for(int j=0;j<2;j++){int i=tid+128*j,r=i>>2,cb=i&3;
            ra[j]=*reinterpret_cast<const float4*>(A+(size_t)r*K+k0+cb*4);}
#pragma unroll
        for(int j=0;j<4;j++){int i=tid+128*j,r=i>>2,cb=i&3;
            rb[j]=*reinterpret_cast<const float4*>(Bm+(size_t)(n0+r)*K+k0+cb*4);}
    };
    auto sts=[&](int buf){
#pragma unroll
        for(int j=0;j<2;j++){int i=tid+128*j,r=i>>2,cb=i&3;
            As[buf][r][cb*4+0]=to_tf32(ra[j].x);As[buf][r][cb*4+1]=to_tf32(ra[j].y);
            As[buf][r][cb*4+2]=to_tf32(ra[j].z);As[buf][r][cb*4+3]=to_tf32(ra[j].w);}
#pragma unroll
        for(int j=0;j<4;j++){int i=tid+128*j,r=i>>2,cb=i&3;
            Bs[buf][r][cb*4+0]=to_tf32(rb[j].x);Bs[buf][r][cb*4+1]=to_tf32(rb[j].y);
            Bs[buf][r][cb*4+2]=to_tf32(rb[j].z);Bs[buf][r][cb*4+3]=to_tf32(rb[j].w);}
    };
    ldg(0);sts(0);__syncthreads();
    const int nst=K/16;
    for(int s=0;s<nst;s++){
        const int cur=s&1;
        if(s+1<nst) ldg((s+1)*16);
#pragma unroll
        for(int kk=0;kk<2;kk++){
            const int kb=kk*8;
            uint32_t af[2][4];
#pragma unroll
            for(int mi=0;mi<2;mi++){int mr=wm*32+mi*16;
                af[mi][0]=__float_as_uint(As[cur][mr+g][kb+t]);
                af[mi][1]=__float_as_uint(As[cur][mr+g+8][kb+t]);
                af[mi][2]=__float_as_uint(As[cur][mr+g][kb+t+4]);
                af[mi][3]=__float_as_uint(As[cur][mr+g+8][kb+t+4]);}
            uint32_t bf[8][2];
#pragma unroll
            for(int ni=0;ni<8;ni++){int nr=wn*64+ni*8+g;
                bf[ni][0]=__float_as_uint(Bs[cur][nr][kb+t]);
                bf[ni][1]=__float_as_uint(Bs[cur][nr][kb+t+4]);}
#pragma unroll
            for(int mi=0;mi<2;mi++)
#pragma unroll
                for(int ni=0;ni<8;ni++) mma_tf32(acc[mi][ni],af[mi],bf[ni]);
        }
        if(s+1<nst) sts(cur^1);
        __syncthreads();
    }
#pragma unroll
    for(int mi=0;mi<2;mi++)
#pragma unroll
      for(int ni=0;ni<8;ni++){
        int row=wm*32+mi*16+g, col=n0+wn*64+ni*8+2*t;
        float b0=bias1[col],b1=bias1[col+1];
        float* p=C+(size_t)row*N+col;
        p[0]=acc[mi][ni][0]+b0; p[1]=acc[mi][ni][1]+b1;
        p=C+(size_t)(row+8)*N+col;
        p[0]=acc[mi][ni][2]+b0; p[1]=acc[mi][ni][3]+b1;
      }
}

// ---- softmax over S per batch row (8 partial slabs) ----
__global__ void __launch_bounds__(256) softmax_kernel(const float* __restrict__ part,float* __restrict__ attn){
    __shared__ float sc[NS];
    __shared__ float wred[8];
    const int b=blockIdx.x,tid=threadIdx.x,lane=tid&31,warp=tid>>5;
    float lmax=-1e30f;
    for(int s=tid;s<NS;s+=256){
        float v=0.f;
#pragma unroll
        for(int p=0;p<8;p++) v+=part[(size_t)p*(NB*NS)+b*NS+s];
        sc[s]=v; lmax=fmaxf(lmax,v);
    }
#pragma unroll
    for(int o=16;o>0;o>>=1) lmax=fmaxf(lmax,__shfl_xor_sync(0xffffffffu,lmax,o));
    if(lane==0) wred[warp]=lmax;
    __syncthreads();
    float m=wred[0];
#pragma unroll
    for(int w=1;w<8;w++) m=fmaxf(m,wred[w]);
    __syncthreads();
    float lsum=0.f;
    for(int s=tid;s<NS;s+=256){float e=expf(sc[s]-m);sc[s]=e;lsum+=e;}
#pragma unroll
    for(int o=16;o>0;o>>=1) lsum+=__shfl_xor_sync(0xffffffffu,lsum,o);
    if(lane==0) wred[warp]=lsum;
    __syncthreads();
    float tot=0.f;
#pragma unroll
    for(int w=0;w<8;w++) tot+=wred[w];
    const float inv=1.f/tot;
    for(int s=tid;s<NS;s+=256) attn[b*NS+s]=sc[s]*inv;
}

// ---- context from bf16 enc ----
__global__ void __launch_bounds__(128) context_kernel(const float* __restrict__ attn,
    const __nv_bfloat16* __restrict__ encb,float* __restrict__ xh0){
    __shared__ float aw[NS];
    const int b=blockIdx.x, p=blockIdx.y*128+threadIdx.x;
    for(int s=threadIdx.x;s<NS;s+=128) aw[s]=attn[b*NS+s];
    __syncthreads();
    const uint32_t* ep=reinterpret_cast<const uint32_t*>(encb+(size_t)b*NS*1024)+p;
    float a0=0.f,a1=0.f;
#pragma unroll 4
    for(int s=0;s<NS;s++){
        uint32_t u=ep[(size_t)s*512];
        __nv_bfloat162 v=*reinterpret_cast<__nv_bfloat162*>(&u);
        float w=aw[s];
        a0+=w*__bfloat162float(v.x);
        a1+=w*__bfloat162float(v.y);
    }
    xh0[b*3072+1024+2*p]=a0;
    xh0[b*3072+1024+2*p+1]=a1;
}

extern "C" void kernel_launch(void* const* d_in,const int* in_sizes,int n_in,
                              void* d_out,int out_size){
    const int*   step = (const int*)  d_in[0];
    const float* h0   = (const float*)d_in[1];
    const float* c0   = (const float*)d_in[2];
    const float* enc  = (const float*)d_in[3];
    const float* emb  = (const float*)d_in[4];
    const float* Wah  = (const float*)d_in[5];
    const float* bah  = (const float*)d_in[6];
    const float* Wae  = (const float*)d_in[7];
    const float* bae  = (const float*)d_in[8];
    const float* va   = (const float*)d_in[9];
    const float* Wih0 = (const float*)d_in[11];
    const float* Whh0 = (const float*)d_in[12];
    const float* bih0 = (const float*)d_in[13];
    const float* bhh0 = (const float*)d_in[14];
    const float* Wih1 = (const float*)d_in[15];
    const float* Whh1 = (const float*)d_in[16];
    const float* bih1 = (const float*)d_in[17];
    const float* bhh1 = (const float*)d_in[18];
    const float* Wout = (const float*)d_in[19];
    const float* bout = (const float*)d_in[20];
    float* out=(float*)d_out;

    float *q,*part,*xh0,*xh1,*h2,*sk;
    __nv_bfloat16 *encb,*waeb;
    cudaGetSymbolAddress((void**)&q,g_q);
    cudaGetSymbolAddress((void**)&part,g_part);
    cudaGetSymbolAddress((void**)&xh0,g_xh0);
    cudaGetSymbolAddress((void**)&xh1,g_xh1);
    cudaGetSymbolAddress((void**)&h2,g_h2);
    cudaGetSymbolAddress((void**)&sk,g_sk);
    cudaGetSymbolAddress((void**)&encb,g_encb);
    cudaGetSymbolAddress((void**)&waeb,g_waeb);

    static cudaStream_t s2=nullptr;
    static cudaEvent_t ev0,ev1;
    if(!s2){
        cudaStreamCreateWithFlags(&s2,cudaStreamNonBlocking);
        cudaEventCreateWithFlags(&ev0,cudaEventDisableTiming);
        cudaEventCreateWithFlags(&ev1,cudaEventDisableTiming);
        cudaFuncSetAttribute(score_kernel,cudaFuncAttributeMaxDynamicSharedMemorySize,SC_SMEM);
    }

    // fork: big enc conversion on s2, q-chain on main stream
    cudaEventRecord(ev0,0);
    cudaStreamWaitEvent(s2,ev0,0);
    cvt_bf16_kernel<<<8192,256,0,s2>>>(enc,encb,(NB*NS*1024)/4);
    cudaEventRecord(ev1,s2);

    cvt_bf16_kernel<<<1024,256>>>(Wae,waeb,(1024*1024)/4);
    stage_kernel<<<64,256>>>(step,emb,h0,xh0,xh1);
    gemm_sk<<<dim3(8,SK),128>>>(h0+64*1024,Wah,Wah,sk,1024,1024,1024,1024/SK);
    reduce_q_kernel<<<256,256>>>(sk,bah,bae,q);

    // join: score needs encb + q
    cudaStreamWaitEvent(0,ev1,0);
    score_kernel<<<dim3(8,512),256,SC_SMEM>>>(encb,waeb,q,va,part);
    softmax_kernel<<<64,256>>>(part,out+OUT_ATT);
    context_kernel<<<dim3(64,4),128>>>(out+OUT_ATT,encb,xh0);
    gemm_sk<<<dim3(32,SK),128>>>(xh0,Wih0,Whh0,sk,4096,2048,3072,3072/SK);
    lstm_red_kernel<<<64,256>>>(sk,bih0,bhh0,c0,out+OUT_H,out+OUT_C,xh1,2048);
    gemm_sk<<<dim3(32,SK),128>>>(xh1,Wih1,Whh1,sk,4096,1024,2048,2048/SK);
    lstm_red_kernel<<<64,256>>>(sk,bih1,bhh1,c0+64*1024,out+OUT_H+64*1024,out+OUT_C+64*1024,h2,1024);
    gemm_tf32_kernel<<<250,128>>>(h2,Wout,out,64,32000,1024,bout);
}